// round 4
// baseline (speedup 1.0000x reference)
#include <cuda_runtime.h>
#include <math_constants.h>
#include <cstdint>

// Problem constants
#define BB 2
#define SS 2048
#define EE 1024
#define HH 16
#define DD 64

// Scratch (device globals — allocation-free rule)
__device__ float g_q[BB * SS * EE];
__device__ float g_k[BB * SS * EE];
__device__ float g_v[BB * SS * EE];
__device__ float g_ctx[BB * SS * EE];

// ---------------------------------------------------------------------------
// tf32 helpers
// ---------------------------------------------------------------------------
__device__ __forceinline__ float f2tf(float f) {
    uint32_t u;
    asm("cvt.rna.tf32.f32 %0, %1;" : "=r"(u) : "f"(f));
    return __uint_as_float(u);
}

__device__ __forceinline__ void mma_tf32(
    float* c, const uint32_t* a, uint32_t b0, uint32_t b1)
{
    asm volatile(
        "mma.sync.aligned.m16n8k8.row.col.f32.tf32.tf32.f32 "
        "{%0,%1,%2,%3},{%4,%5,%6,%7},{%8,%9},{%0,%1,%2,%3};\n"
        : "+f"(c[0]), "+f"(c[1]), "+f"(c[2]), "+f"(c[3])
        : "r"(a[0]), "r"(a[1]), "r"(a[2]), "r"(a[3]), "r"(b0), "r"(b1));
}

// ---------------------------------------------------------------------------
// tf32 tensor-core SGEMM: C[M,N] = A[M,K] @ W[K,N] + bias
// BM=128, BN=128, BK=16, 256 threads (8 warps as 4x2), warp tile 32x64.
// A smem is pair-permuted along k (logical (t,t+4) physically adjacent)
// so A-fragments are 2x LDS.64.
// MODE: 0 = fp32 out, 1 = tf32-rounded out, 2 = tf32-rounded + 0.125 scale
// ---------------------------------------------------------------------------
#define GBM 128
#define GBN 128
#define GBK 16
#define APITCH 20
#define BPITCH 132

template<int MODE>
__global__ __launch_bounds__(256, 2) void sgemm_tf32(
    const float* __restrict__ A, const float* __restrict__ W,
    const float* __restrict__ bias, float* __restrict__ C,
    int M, int N, int K)
{
    __shared__ float As[2][GBM * APITCH];
    __shared__ float Bs[2][GBK * BPITCH];

    const int tid  = threadIdx.x;
    const int lane = tid & 31;
    const int warp = tid >> 5;
    const int gid  = lane >> 2;   // 0..7
    const int tig  = lane & 3;    // 0..3
    const int wm   = warp >> 1;   // 0..3
    const int wn   = warp & 1;    // 0..1
    const int m0   = blockIdx.y * GBM;
    const int n0   = blockIdx.x * GBN;

    const int arow = tid >> 1;            // 0..127
    const int akq  = (tid & 1) * 8;       // 0 or 8 (full 8-group)
    const int brow = tid >> 4;            // 0..15
    const int bcol = (tid & 15) * 8;      // 0..120

    float acc[2][8][4] = {};

    // prologue: stage tile 0
    {
        float4 a0 = *(const float4*)&A[(size_t)(m0 + arow) * K + akq];
        float4 a1 = *(const float4*)&A[(size_t)(m0 + arow) * K + akq + 4];
        float2* as = (float2*)&As[0][arow * APITCH + akq];
        as[0] = make_float2(f2tf(a0.x), f2tf(a1.x));
        as[1] = make_float2(f2tf(a0.y), f2tf(a1.y));
        as[2] = make_float2(f2tf(a0.z), f2tf(a1.z));
        as[3] = make_float2(f2tf(a0.w), f2tf(a1.w));
        float4 b0 = *(const float4*)&W[(size_t)brow * N + n0 + bcol];
        float4 b1 = *(const float4*)&W[(size_t)brow * N + n0 + bcol + 4];
        float* bs = &Bs[0][brow * BPITCH + bcol];
        bs[0] = f2tf(b0.x); bs[1] = f2tf(b0.y); bs[2] = f2tf(b0.z); bs[3] = f2tf(b0.w);
        bs[4] = f2tf(b1.x); bs[5] = f2tf(b1.y); bs[6] = f2tf(b1.z); bs[7] = f2tf(b1.w);
    }
    __syncthreads();

    int buf = 0;
    for (int kt = 0; kt < K; kt += GBK) {
        const bool has_next = (kt + GBK) < K;
        float4 ra0, ra1, rb0, rb1;
        if (has_next) {
            ra0 = *(const float4*)&A[(size_t)(m0 + arow) * K + kt + GBK + akq];
            ra1 = *(const float4*)&A[(size_t)(m0 + arow) * K + kt + GBK + akq + 4];
            rb0 = *(const float4*)&W[(size_t)(kt + GBK + brow) * N + n0 + bcol];
            rb1 = *(const float4*)&W[(size_t)(kt + GBK + brow) * N + n0 + bcol + 4];
        }

        const float* as = As[buf];
        const float* bs = Bs[buf];
        #pragma unroll
        for (int ks = 0; ks < 2; ks++) {
            uint32_t af[2][4];
            #pragma unroll
            for (int i = 0; i < 2; i++) {
                int mr = wm * 32 + i * 16 + gid;
                float2 q0 = *(const float2*)&as[(mr    ) * APITCH + ks * 8 + 2 * tig];
                float2 q1 = *(const float2*)&as[(mr + 8) * APITCH + ks * 8 + 2 * tig];
                af[i][0] = __float_as_uint(q0.x);
                af[i][1] = __float_as_uint(q1.x);
                af[i][2] = __float_as_uint(q0.y);
                af[i][3] = __float_as_uint(q1.y);
            }
            #pragma unroll
            for (int j = 0; j < 8; j++) {
                int nc = wn * 64 + j * 8 + gid;
                uint32_t b0 = __float_as_uint(bs[(ks * 8 + tig    ) * BPITCH + nc]);
                uint32_t b1 = __float_as_uint(bs[(ks * 8 + tig + 4) * BPITCH + nc]);
                #pragma unroll
                for (int i = 0; i < 2; i++)
                    mma_tf32(acc[i][j], af[i], b0, b1);
            }
        }

        if (has_next) {
            float2* asn = (float2*)&As[buf ^ 1][arow * APITCH + akq];
            asn[0] = make_float2(f2tf(ra0.x), f2tf(ra1.x));
            asn[1] = make_float2(f2tf(ra0.y), f2tf(ra1.y));
            asn[2] = make_float2(f2tf(ra0.z), f2tf(ra1.z));
            asn[3] = make_float2(f2tf(ra0.w), f2tf(ra1.w));
            float* bsn = &Bs[buf ^ 1][brow * BPITCH + bcol];
            bsn[0] = f2tf(rb0.x); bsn[1] = f2tf(rb0.y); bsn[2] = f2tf(rb0.z); bsn[3] = f2tf(rb0.w);
            bsn[4] = f2tf(rb1.x); bsn[5] = f2tf(rb1.y); bsn[6] = f2tf(rb1.z); bsn[7] = f2tf(rb1.w);
            __syncthreads();
            buf ^= 1;
        }
    }

    // epilogue
    #pragma unroll
    for (int i = 0; i < 2; i++) {
        int r = m0 + wm * 32 + i * 16 + gid;
        #pragma unroll
        for (int j = 0; j < 8; j++) {
            int c = n0 + wn * 64 + j * 8 + 2 * tig;
            float2 bb = *(const float2*)&bias[c];
            float v00 = acc[i][j][0] + bb.x;
            float v01 = acc[i][j][1] + bb.y;
            float v10 = acc[i][j][2] + bb.x;
            float v11 = acc[i][j][3] + bb.y;
            if (MODE == 2) { v00 *= 0.125f; v01 *= 0.125f; v10 *= 0.125f; v11 *= 0.125f; }
            if (MODE >= 1) { v00 = f2tf(v00); v01 = f2tf(v01); v10 = f2tf(v10); v11 = f2tf(v11); }
            *(float2*)&C[(size_t)r * N + c]       = make_float2(v00, v01);
            *(float2*)&C[(size_t)(r + 8) * N + c] = make_float2(v10, v11);
        }
    }
}

// ---------------------------------------------------------------------------
// tf32 tensor-core causal flash attention.
// Inputs pre-rounded to tf32 (Q additionally pre-scaled by 1/sqrt(D)).
// CTA: 64 q rows (4 warps x m16). K tile 64. D=64.
// smem layouts pair-permuted along k so fragments load as LDS.64:
//   Ks[key][d_perm], Vt[d][key_perm], Ps[q][key_perm], pitch 72.
// ---------------------------------------------------------------------------
#define KP 72

__global__ __launch_bounds__(128, 4) void flash_attn_tc(
    const float* __restrict__ Qg, const float* __restrict__ Kg,
    const float* __restrict__ Vg, float* __restrict__ ctx)
{
    extern __shared__ float sm[];
    float* Ks = sm;               // [64][KP]
    float* Vt = sm + 64 * KP;     // [64][KP]  rows = d, cols = key (permuted)
    float* Ps = sm + 128 * KP;    // [64][KP]

    const int tid  = threadIdx.x;
    const int lane = tid & 31;
    const int warp = tid >> 5;      // 0..3
    const int gid  = lane >> 2;
    const int tig  = lane & 3;
    const int qt   = (int)gridDim.x - 1 - (int)blockIdx.x;  // heavy tiles first
    const int h    = blockIdx.y;
    const int b    = blockIdx.z;
    const int q0   = qt * 64;
    const int wrow = warp * 16;

    const size_t base = (size_t)b * SS * EE + (size_t)h * DD;

    const int grow = tid >> 1;          // 0..63 (row within tile)
    const int gh   = (tid & 1) * 32;    // 0 or 32 (col half)
    // permuted destination column for this thread's key row (V transpose)
    const int vcol = (grow & ~7) + ((grow & 3) * 2 + ((grow >> 2) & 1));

    // ---- stage Q (pre-scaled, pre-tf32) into Ks with k-pair permute ----
    {
        const float* qrow = &Qg[base + (size_t)(q0 + grow) * EE];
        #pragma unroll
        for (int g = 0; g < 4; g++) {
            int dbase = gh + g * 8;
            float4 lo = *(const float4*)&qrow[dbase];
            float4 hi = *(const float4*)&qrow[dbase + 4];
            float2* d = (float2*)&Ks[grow * KP + dbase];
            d[0] = make_float2(lo.x, hi.x);
            d[1] = make_float2(lo.y, hi.y);
            d[2] = make_float2(lo.z, hi.z);
            d[3] = make_float2(lo.w, hi.w);
        }
    }
    __syncthreads();

    uint32_t qf[8][4];
    #pragma unroll
    for (int ks = 0; ks < 8; ks++) {
        int r = wrow + gid;
        float2 q0v = *(const float2*)&Ks[(r    ) * KP + ks * 8 + 2 * tig];
        float2 q1v = *(const float2*)&Ks[(r + 8) * KP + ks * 8 + 2 * tig];
        qf[ks][0] = __float_as_uint(q0v.x);
        qf[ks][1] = __float_as_uint(q1v.x);
        qf[ks][2] = __float_as_uint(q0v.y);
        qf[ks][3] = __float_as_uint(q1v.y);
    }

    float oacc[8][4] = {};
    float m0r = -CUDART_INF_F, m1r = -CUDART_INF_F;
    float l0 = 0.f, l1 = 0.f;
    const int r0g = q0 + wrow + gid;
    const int r1g = r0g + 8;
    // physical slot of logical col 2*tig in a pair-permuted 8-group
    const int p0 = (tig & 1) * 4 + (tig >> 1);

    for (int kt = 0; kt <= qt; kt++) {
        const int k0 = kt * 64;
        __syncthreads();  // everyone done reading Ks/Vt

        // stage K (row-major, k-pair permuted) and V (transposed, key-pair permuted)
        {
            const float* krow = &Kg[base + (size_t)(k0 + grow) * EE];
            const float* vrow = &Vg[base + (size_t)(k0 + grow) * EE];
            #pragma unroll
            for (int g = 0; g < 4; g++) {
                int dbase = gh + g * 8;
                float4 lo = *(const float4*)&krow[dbase];
                float4 hi = *(const float4*)&krow[dbase + 4];
                float2* d = (float2*)&Ks[grow * KP + dbase];
                d[0] = make_float2(lo.x, hi.x);
                d[1] = make_float2(lo.y, hi.y);
                d[2] = make_float2(lo.z, hi.z);
                d[3] = make_float2(lo.w, hi.w);
                float4 vlo = *(const float4*)&vrow[dbase];
                float4 vhi = *(const float4*)&vrow[dbase + 4];
                Vt[(dbase + 0) * KP + vcol] = vlo.x;
                Vt[(dbase + 1) * KP + vcol] = vlo.y;
                Vt[(dbase + 2) * KP + vcol] = vlo.z;
                Vt[(dbase + 3) * KP + vcol] = vlo.w;
                Vt[(dbase + 4) * KP + vcol] = vhi.x;
                Vt[(dbase + 5) * KP + vcol] = vhi.y;
                Vt[(dbase + 6) * KP + vcol] = vhi.z;
                Vt[(dbase + 7) * KP + vcol] = vhi.w;
            }
        }
        __syncthreads();

        // S = Q @ K^T
        float sacc[8][4] = {};
        #pragma unroll
        for (int t = 0; t < 8; t++) {
            #pragma unroll
            for (int ks = 0; ks < 8; ks++) {
                float2 bv = *(const float2*)&Ks[(t * 8 + gid) * KP + ks * 8 + 2 * tig];
                mma_tf32(sacc[t], qf[ks],
                         __float_as_uint(bv.x), __float_as_uint(bv.y));
            }
        }

        // causal mask (diagonal tile only)
        if (kt == qt) {
            #pragma unroll
            for (int t = 0; t < 8; t++) {
                int c = k0 + t * 8 + 2 * tig;
                if (c     > r0g) sacc[t][0] = -CUDART_INF_F;
                if (c + 1 > r0g) sacc[t][1] = -CUDART_INF_F;
                if (c     > r1g) sacc[t][2] = -CUDART_INF_F;
                if (c + 1 > r1g) sacc[t][3] = -CUDART_INF_F;
            }
        }

        // online softmax
        float vm0 = -CUDART_INF_F, vm1 = -CUDART_INF_F;
        #pragma unroll
        for (int t = 0; t < 8; t++) {
            vm0 = fmaxf(vm0, fmaxf(sacc[t][0], sacc[t][1]));
            vm1 = fmaxf(vm1, fmaxf(sacc[t][2], sacc[t][3]));
        }
        vm0 = fmaxf(vm0, __shfl_xor_sync(0xffffffffu, vm0, 1));
        vm0 = fmaxf(vm0, __shfl_xor_sync(0xffffffffu, vm0, 2));
        vm1 = fmaxf(vm1, __shfl_xor_sync(0xffffffffu, vm1, 1));
        vm1 = fmaxf(vm1, __shfl_xor_sync(0xffffffffu, vm1, 2));

        float mn0 = fmaxf(m0r, vm0), mn1 = fmaxf(m1r, vm1);
        float al0 = __expf(m0r - mn0), al1 = __expf(m1r - mn1);

        float sum0 = 0.f, sum1 = 0.f;
        #pragma unroll
        for (int t = 0; t < 8; t++) {
            float pv0 = __expf(sacc[t][0] - mn0);
            float pv1 = __expf(sacc[t][1] - mn0);
            float pv2 = __expf(sacc[t][2] - mn1);
            float pv3 = __expf(sacc[t][3] - mn1);
            sacc[t][0] = pv0; sacc[t][1] = pv1; sacc[t][2] = pv2; sacc[t][3] = pv3;
            sum0 += pv0 + pv1;
            sum1 += pv2 + pv3;
        }
        sum0 += __shfl_xor_sync(0xffffffffu, sum0, 1);
        sum0 += __shfl_xor_sync(0xffffffffu, sum0, 2);
        sum1 += __shfl_xor_sync(0xffffffffu, sum1, 1);
        sum1 += __shfl_xor_sync(0xffffffffu, sum1, 2);

        l0 = l0 * al0 + sum0;  m0r = mn0;
        l1 = l1 * al1 + sum1;  m1r = mn1;
        #pragma unroll
        for (int dt = 0; dt < 8; dt++) {
            oacc[dt][0] *= al0; oacc[dt][1] *= al0;
            oacc[dt][2] *= al1; oacc[dt][3] *= al1;
        }

        // stage P (tf32, key-pair permuted). per-warp rows -> syncwarp only
        {
            int pr = wrow + gid;
            #pragma unroll
            for (int t = 0; t < 8; t++) {
                Ps[(pr    ) * KP + t * 8 + p0    ] = f2tf(sacc[t][0]);
                Ps[(pr    ) * KP + t * 8 + p0 + 2] = f2tf(sacc[t][1]);
                Ps[(pr + 8) * KP + t * 8 + p0    ] = f2tf(sacc[t][2]);
                Ps[(pr + 8) * KP + t * 8 + p0 + 2] = f2tf(sacc[t][3]);
            }
        }
        __syncwarp();

        // O += P @ V
        #pragma unroll
        for (int ks = 0; ks < 8; ks++) {
            int pr = wrow + gid;
            float2 pa0 = *(const float2*)&Ps[(pr    ) * KP + ks * 8 + 2 * tig];
            float2 pa1 = *(const float2*)&Ps[(pr + 8) * KP + ks * 8 + 2 * tig];
            uint32_t af[4];
            af[0] = __float_as_uint(pa0.x);
            af[1] = __float_as_uint(pa1.x);
            af[2] = __float_as_uint(pa0.y);
            af[3] = __float_as_uint(pa1.y);
            #pragma unroll
            for (int dt = 0; dt < 8; dt++) {
                float2 bv = *(const float2*)&Vt[(dt * 8 + gid) * KP + ks * 8 + 2 * tig];
                mma_tf32(oacc[dt], af,
                         __float_as_uint(bv.x), __float_as_uint(bv.y));
            }
        }
    }

    // normalize + store
    float inv0 = 1.f / l0, inv1 = 1.f / l1;
    #pragma unroll
    for (int dt = 0; dt < 8; dt++) {
        int c = dt * 8 + 2 * tig;
        *(float2*)&ctx[base + (size_t)r0g * EE + c] =
            make_float2(oacc[dt][0] * inv0, oacc[dt][1] * inv0);
        *(float2*)&ctx[base + (size_t)r1g * EE + c] =
            make_float2(oacc[dt][2] * inv1, oacc[dt][3] * inv1);
    }
}

// ---------------------------------------------------------------------------
// Launch
// ---------------------------------------------------------------------------
extern "C" void kernel_launch(void* const* d_in, const int* in_sizes, int n_in,
                              void* d_out, int out_size)
{
    (void)in_sizes; (void)n_in; (void)out_size;
    const float* x  = (const float*)d_in[0];
    const float* Wq = (const float*)d_in[1];
    const float* bq = (const float*)d_in[2];
    const float* Wk = (const float*)d_in[3];
    const float* bk = (const float*)d_in[4];
    const float* Wv = (const float*)d_in[5];
    const float* bv = (const float*)d_in[6];
    const float* Wo = (const float*)d_in[7];
    const float* bo = (const float*)d_in[8];
    float* out = (float*)d_out;

    float *qp, *kp, *vp, *cp;
    cudaGetSymbolAddress((void**)&qp, g_q);
    cudaGetSymbolAddress((void**)&kp, g_k);
    cudaGetSymbolAddress((void**)&vp, g_v);
    cudaGetSymbolAddress((void**)&cp, g_ctx);

    const int M = BB * SS, N = EE, K = EE;
    dim3 gg(N / GBN, M / GBM);  // (8, 32)

    sgemm_tf32<2><<<gg, 256>>>(x, Wq, bq, qp, M, N, K);  // q: scaled + tf32
    sgemm_tf32<1><<<gg, 256>>>(x, Wk, bk, kp, M, N, K);  // k: tf32
    sgemm_tf32<1><<<gg, 256>>>(x, Wv, bv, vp, M, N, K);  // v: tf32

    const int smem = 3 * 64 * KP * (int)sizeof(float);   // 55296
    cudaFuncSetAttribute(flash_attn_tc, cudaFuncAttributeMaxDynamicSharedMemorySize, smem);
    flash_attn_tc<<<dim3(SS / 64, HH, BB), 128, smem>>>(qp, kp, vp, cp);

    sgemm_tf32<0><<<gg, 256>>>(cp, Wo, bo, out, M, N, K);  // final: fp32
}

// round 5
// speedup vs baseline: 1.1417x; 1.1417x over previous
#include <cuda_runtime.h>
#include <math_constants.h>
#include <cstdint>

// Problem constants
#define BB 2
#define SS 2048
#define EE 1024
#define HH 16
#define DD 64

// Scratch (device globals — allocation-free rule)
__device__ float g_q[BB * SS * EE];
__device__ float g_k[BB * SS * EE];
__device__ float g_v[BB * SS * EE];
__device__ float g_ctx[BB * SS * EE];

// ---------------------------------------------------------------------------
// tf32 helpers
// ---------------------------------------------------------------------------
__device__ __forceinline__ float f2tf(float f) {
    uint32_t u;
    asm("cvt.rna.tf32.f32 %0, %1;" : "=r"(u) : "f"(f));
    return __uint_as_float(u);
}

__device__ __forceinline__ void mma_tf32(
    float* c, const uint32_t* a, uint32_t b0, uint32_t b1)
{
    asm volatile(
        "mma.sync.aligned.m16n8k8.row.col.f32.tf32.tf32.f32 "
        "{%0,%1,%2,%3},{%4,%5,%6,%7},{%8,%9},{%0,%1,%2,%3};\n"
        : "+f"(c[0]), "+f"(c[1]), "+f"(c[2]), "+f"(c[3])
        : "r"(a[0]), "r"(a[1]), "r"(a[2]), "r"(a[3]), "r"(b0), "r"(b1));
}

__device__ __forceinline__ void cp16(uint32_t smem_dst, const float* gsrc) {
    asm volatile("cp.async.cg.shared.global [%0], [%1], 16;\n"
                 :: "r"(smem_dst), "l"(gsrc));
}
__device__ __forceinline__ void cp_commit() {
    asm volatile("cp.async.commit_group;\n");
}
template<int N>
__device__ __forceinline__ void cp_wait() {
    asm volatile("cp.async.wait_group %0;\n" :: "n"(N));
}

// ---------------------------------------------------------------------------
// tf32 tensor-core GEMM body: C[M,N] = A[M,K] @ W[K,N] + bias
// BM=128, BN=128, BK=16, 256 threads (8 warps as 4x2), warp tile 32x64.
// mode: 0 = fp32 out, 1 = tf32-rounded out, 2 = tf32-rounded + 0.125 scale
// ---------------------------------------------------------------------------
#define GBM 128
#define GBN 128
#define GBK 16
#define APITCH 20
#define BPITCH 132

__device__ __forceinline__ void gemm_body(
    const float* __restrict__ A, const float* __restrict__ W,
    const float* __restrict__ bias, float* __restrict__ C,
    int M, int N, int K, int mode)
{
    __shared__ float As[2][GBM * APITCH];
    __shared__ float Bs[2][GBK * BPITCH];

    const int tid  = threadIdx.x;
    const int lane = tid & 31;
    const int warp = tid >> 5;
    const int gid  = lane >> 2;
    const int tig  = lane & 3;
    const int wm   = warp >> 1;
    const int wn   = warp & 1;
    const int m0   = blockIdx.y * GBM;
    const int n0   = blockIdx.x * GBN;

    const int arow = tid >> 1;
    const int akq  = (tid & 1) * 8;
    const int brow = tid >> 4;
    const int bcol = (tid & 15) * 8;

    float acc[2][8][4] = {};

    {
        float4 a0 = *(const float4*)&A[(size_t)(m0 + arow) * K + akq];
        float4 a1 = *(const float4*)&A[(size_t)(m0 + arow) * K + akq + 4];
        float2* as = (float2*)&As[0][arow * APITCH + akq];
        as[0] = make_float2(f2tf(a0.x), f2tf(a1.x));
        as[1] = make_float2(f2tf(a0.y), f2tf(a1.y));
        as[2] = make_float2(f2tf(a0.z), f2tf(a1.z));
        as[3] = make_float2(f2tf(a0.w), f2tf(a1.w));
        float4 b0 = *(const float4*)&W[(size_t)brow * N + n0 + bcol];
        float4 b1 = *(const float4*)&W[(size_t)brow * N + n0 + bcol + 4];
        float* bs = &Bs[0][brow * BPITCH + bcol];
        bs[0] = f2tf(b0.x); bs[1] = f2tf(b0.y); bs[2] = f2tf(b0.z); bs[3] = f2tf(b0.w);
        bs[4] = f2tf(b1.x); bs[5] = f2tf(b1.y); bs[6] = f2tf(b1.z); bs[7] = f2tf(b1.w);
    }
    __syncthreads();

    int buf = 0;
    for (int kt = 0; kt < K; kt += GBK) {
        const bool has_next = (kt + GBK) < K;
        float4 ra0, ra1, rb0, rb1;
        if (has_next) {
            ra0 = *(const float4*)&A[(size_t)(m0 + arow) * K + kt + GBK + akq];
            ra1 = *(const float4*)&A[(size_t)(m0 + arow) * K + kt + GBK + akq + 4];
            rb0 = *(const float4*)&W[(size_t)(kt + GBK + brow) * N + n0 + bcol];
            rb1 = *(const float4*)&W[(size_t)(kt + GBK + brow) * N + n0 + bcol + 4];
        }

        const float* as = As[buf];
        const float* bs = Bs[buf];
        #pragma unroll
        for (int ks = 0; ks < 2; ks++) {
            uint32_t af[2][4];
            #pragma unroll
            for (int i = 0; i < 2; i++) {
                int mr = wm * 32 + i * 16 + gid;
                float2 q0 = *(const float2*)&as[(mr    ) * APITCH + ks * 8 + 2 * tig];
                float2 q1 = *(const float2*)&as[(mr + 8) * APITCH + ks * 8 + 2 * tig];
                af[i][0] = __float_as_uint(q0.x);
                af[i][1] = __float_as_uint(q1.x);
                af[i][2] = __float_as_uint(q0.y);
                af[i][3] = __float_as_uint(q1.y);
            }
            #pragma unroll
            for (int j = 0; j < 8; j++) {
                int nc = wn * 64 + j * 8 + gid;
                uint32_t b0 = __float_as_uint(bs[(ks * 8 + tig    ) * BPITCH + nc]);
                uint32_t b1 = __float_as_uint(bs[(ks * 8 + tig + 4) * BPITCH + nc]);
                #pragma unroll
                for (int i = 0; i < 2; i++)
                    mma_tf32(acc[i][j], af[i], b0, b1);
            }
        }

        if (has_next) {
            float2* asn = (float2*)&As[buf ^ 1][arow * APITCH + akq];
            asn[0] = make_float2(f2tf(ra0.x), f2tf(ra1.x));
            asn[1] = make_float2(f2tf(ra0.y), f2tf(ra1.y));
            asn[2] = make_float2(f2tf(ra0.z), f2tf(ra1.z));
            asn[3] = make_float2(f2tf(ra0.w), f2tf(ra1.w));
            float* bsn = &Bs[buf ^ 1][brow * BPITCH + bcol];
            bsn[0] = f2tf(rb0.x); bsn[1] = f2tf(rb0.y); bsn[2] = f2tf(rb0.z); bsn[3] = f2tf(rb0.w);
            bsn[4] = f2tf(rb1.x); bsn[5] = f2tf(rb1.y); bsn[6] = f2tf(rb1.z); bsn[7] = f2tf(rb1.w);
            __syncthreads();
            buf ^= 1;
        }
    }

    #pragma unroll
    for (int i = 0; i < 2; i++) {
        int r = m0 + wm * 32 + i * 16 + gid;
        #pragma unroll
        for (int j = 0; j < 8; j++) {
            int c = n0 + wn * 64 + j * 8 + 2 * tig;
            float2 bb = *(const float2*)&bias[c];
            float v00 = acc[i][j][0] + bb.x;
            float v01 = acc[i][j][1] + bb.y;
            float v10 = acc[i][j][2] + bb.x;
            float v11 = acc[i][j][3] + bb.y;
            if (mode == 2) { v00 *= 0.125f; v01 *= 0.125f; v10 *= 0.125f; v11 *= 0.125f; }
            if (mode >= 1) { v00 = f2tf(v00); v01 = f2tf(v01); v10 = f2tf(v10); v11 = f2tf(v11); }
            *(float2*)&C[(size_t)r * N + c]       = make_float2(v00, v01);
            *(float2*)&C[(size_t)(r + 8) * N + c] = make_float2(v10, v11);
        }
    }
}

// Merged QKV projection: blockIdx.z selects q/k/v
__global__ __launch_bounds__(256, 2) void sgemm_qkv(
    const float* __restrict__ x,
    const float* __restrict__ Wq, const float* __restrict__ bq,
    const float* __restrict__ Wk, const float* __restrict__ bk,
    const float* __restrict__ Wv, const float* __restrict__ bv,
    float* __restrict__ qp, float* __restrict__ kp, float* __restrict__ vp)
{
    const int z = blockIdx.z;
    const float* W  = (z == 0) ? Wq : (z == 1) ? Wk : Wv;
    const float* bb = (z == 0) ? bq : (z == 1) ? bk : bv;
    float* C        = (z == 0) ? qp : (z == 1) ? kp : vp;
    gemm_body(x, W, bb, C, BB * SS, EE, EE, (z == 0) ? 2 : 1);
}

__global__ __launch_bounds__(256, 2) void sgemm_out(
    const float* __restrict__ A, const float* __restrict__ W,
    const float* __restrict__ bias, float* __restrict__ C)
{
    gemm_body(A, W, bias, C, BB * SS, EE, EE, 0);
}

// ---------------------------------------------------------------------------
// tf32 flash attention, causal. 256 threads = 8 warps.
// Warps 0-3: q rows [q0, q0+64); warps 4-7: [q0+64, q0+128).
// K/V tiles (64 keys x 64 d, pre-tf32) double-buffered via cp.async.
// Plain row-major smem, pitch 72 (conflict-free scalar frag loads).
// smem: Ks[2][64*72] + Vs[2][64*72] + Ps[128*72] = 110592 B -> 2 CTA/SM.
// ---------------------------------------------------------------------------
#define KP 72

__global__ __launch_bounds__(256, 2) void flash_attn_tc(
    const float* __restrict__ Qg, const float* __restrict__ Kg,
    const float* __restrict__ Vg, float* __restrict__ ctx)
{
    extern __shared__ float sm[];
    float* Ks0 = sm;
    float* Ks1 = sm + 64 * KP;
    float* Vs0 = sm + 2 * 64 * KP;
    float* Vs1 = sm + 3 * 64 * KP;
    float* Ps  = sm + 4 * 64 * KP;   // [128][KP]

    const int tid  = threadIdx.x;
    const int lane = tid & 31;
    const int warp = tid >> 5;              // 0..7
    const int gid  = lane >> 2;
    const int tig  = lane & 3;
    const int qt2  = (int)gridDim.x - 1 - (int)blockIdx.x;  // heavy first
    const int h    = blockIdx.y;
    const int b    = blockIdx.z;
    const int q0   = qt2 * 128;
    const int wloc = (warp >> 2) * 64 + (warp & 3) * 16;    // local row base
    const int wbase = q0 + wloc;
    const int nt   = 2 * qt2 + 2;

    const size_t base = (size_t)b * SS * EE + (size_t)h * DD;

    // cp.async staging: 256 threads cover 64 rows x 64 cols (16 floats/thread)
    const int srow = tid >> 2;
    const int scol = (tid & 3) * 16;
    const uint32_t ks_dst0 = (uint32_t)__cvta_generic_to_shared(&Ks0[srow * KP + scol]);
    const uint32_t ks_dst1 = (uint32_t)__cvta_generic_to_shared(&Ks1[srow * KP + scol]);
    const uint32_t vs_dst0 = (uint32_t)__cvta_generic_to_shared(&Vs0[srow * KP + scol]);
    const uint32_t vs_dst1 = (uint32_t)__cvta_generic_to_shared(&Vs1[srow * KP + scol]);

    // prologue: prefetch tile 0 into buffer 0
    {
        const float* kg = &Kg[base + (size_t)srow * EE + scol];
        const float* vg = &Vg[base + (size_t)srow * EE + scol];
        #pragma unroll
        for (int c = 0; c < 16; c += 4) {
            cp16(ks_dst0 + c * 4, kg + c);
            cp16(vs_dst0 + c * 4, vg + c);
        }
        cp_commit();
    }

    // stage Q (pre-scaled, pre-tf32) into Ps, then build fragments
    {
        const int qrow = tid >> 1;          // 0..127
        const int qh   = (tid & 1) * 32;
        const float* qsrc = &Qg[base + (size_t)(q0 + qrow) * EE + qh];
        float* d = &Ps[qrow * KP + qh];
        #pragma unroll
        for (int u = 0; u < 8; u++)
            *(float4*)&d[u * 4] = *(const float4*)&qsrc[u * 4];
    }
    __syncthreads();

    uint32_t qf[8][4];
    #pragma unroll
    for (int ks = 0; ks < 8; ks++) {
        int r = wloc + gid;
        qf[ks][0] = __float_as_uint(Ps[(r    ) * KP + ks * 8 + tig    ]);
        qf[ks][1] = __float_as_uint(Ps[(r + 8) * KP + ks * 8 + tig    ]);
        qf[ks][2] = __float_as_uint(Ps[(r    ) * KP + ks * 8 + tig + 4]);
        qf[ks][3] = __float_as_uint(Ps[(r + 8) * KP + ks * 8 + tig + 4]);
    }

    float oacc[8][4] = {};
    float m0r = -CUDART_INF_F, m1r = -CUDART_INF_F;
    float l0 = 0.f, l1 = 0.f;
    const int r0g = wbase + gid;
    const int r1g = r0g + 8;

    for (int kt = 0; kt < nt; kt++) {
        const int k0 = kt * 64;
        const int buf = kt & 1;

        // prefetch next tile into other buffer (previous compute on it is synced)
        if (kt + 1 < nt) {
            const int kn = (kt + 1) * 64;
            const float* kg = &Kg[base + (size_t)(kn + srow) * EE + scol];
            const float* vg = &Vg[base + (size_t)(kn + srow) * EE + scol];
            const uint32_t kd = buf ? ks_dst0 : ks_dst1;
            const uint32_t vd = buf ? vs_dst0 : vs_dst1;
            #pragma unroll
            for (int c = 0; c < 16; c += 4) {
                cp16(kd + c * 4, kg + c);
                cp16(vd + c * 4, vg + c);
            }
            cp_commit();
            cp_wait<1>();   // tile kt complete
        } else {
            cp_wait<0>();
        }
        __syncthreads();

        const float* Ks_ = buf ? Ks1 : Ks0;
        const float* Vs_ = buf ? Vs1 : Vs0;

        // S = Q @ K^T
        float sacc[8][4] = {};
        #pragma unroll
        for (int t = 0; t < 8; t++) {
            #pragma unroll
            for (int ks = 0; ks < 8; ks++) {
                uint32_t b0 = __float_as_uint(Ks_[(t * 8 + gid) * KP + ks * 8 + tig    ]);
                uint32_t b1 = __float_as_uint(Ks_[(t * 8 + gid) * KP + ks * 8 + tig + 4]);
                mma_tf32(sacc[t], qf[ks], b0, b1);
            }
        }

        // causal mask: needed iff this tile reaches past the warp's first row
        if (k0 + 63 > wbase) {
            #pragma unroll
            for (int t = 0; t < 8; t++) {
                int c = k0 + t * 8 + 2 * tig;
                if (c     > r0g) sacc[t][0] = -CUDART_INF_F;
                if (c + 1 > r0g) sacc[t][1] = -CUDART_INF_F;
                if (c     > r1g) sacc[t][2] = -CUDART_INF_F;
                if (c + 1 > r1g) sacc[t][3] = -CUDART_INF_F;
            }
        }

        // online softmax (per-warp rows)
        float vm0 = -CUDART_INF_F, vm1 = -CUDART_INF_F;
        #pragma unroll
        for (int t = 0; t < 8; t++) {
            vm0 = fmaxf(vm0, fmaxf(sacc[t][0], sacc[t][1]));
            vm1 = fmaxf(vm1, fmaxf(sacc[t][2], sacc[t][3]));
        }
        vm0 = fmaxf(vm0, __shfl_xor_sync(0xffffffffu, vm0, 1));
        vm0 = fmaxf(vm0, __shfl_xor_sync(0xffffffffu, vm0, 2));
        vm1 = fmaxf(vm1, __shfl_xor_sync(0xffffffffu, vm1, 1));
        vm1 = fmaxf(vm1, __shfl_xor_sync(0xffffffffu, vm1, 2));

        float mn0 = fmaxf(m0r, vm0), mn1 = fmaxf(m1r, vm1);
        float al0 = __expf(m0r - mn0), al1 = __expf(m1r - mn1);

        float sum0 = 0.f, sum1 = 0.f;
        #pragma unroll
        for (int t = 0; t < 8; t++) {
            float pv0 = __expf(sacc[t][0] - mn0);
            float pv1 = __expf(sacc[t][1] - mn0);
            float pv2 = __expf(sacc[t][2] - mn1);
            float pv3 = __expf(sacc[t][3] - mn1);
            sacc[t][0] = pv0; sacc[t][1] = pv1; sacc[t][2] = pv2; sacc[t][3] = pv3;
            sum0 += pv0 + pv1;
            sum1 += pv2 + pv3;
        }
        sum0 += __shfl_xor_sync(0xffffffffu, sum0, 1);
        sum0 += __shfl_xor_sync(0xffffffffu, sum0, 2);
        sum1 += __shfl_xor_sync(0xffffffffu, sum1, 1);
        sum1 += __shfl_xor_sync(0xffffffffu, sum1, 2);

        l0 = l0 * al0 + sum0;  m0r = mn0;
        l1 = l1 * al1 + sum1;  m1r = mn1;
        #pragma unroll
        for (int dt = 0; dt < 8; dt++) {
            oacc[dt][0] *= al0; oacc[dt][1] *= al0;
            oacc[dt][2] *= al1; oacc[dt][3] *= al1;
        }

        // stage P (tf32) into own rows; warp-local ordering only
        {
            int pr = wloc + gid;
            #pragma unroll
            for (int t = 0; t < 8; t++) {
                *(float2*)&Ps[(pr    ) * KP + t * 8 + 2 * tig] =
                    make_float2(f2tf(sacc[t][0]), f2tf(sacc[t][1]));
                *(float2*)&Ps[(pr + 8) * KP + t * 8 + 2 * tig] =
                    make_float2(f2tf(sacc[t][2]), f2tf(sacc[t][3]));
            }
        }
        __syncwarp();

        // O += P @ V
        #pragma unroll
        for (int ks = 0; ks < 8; ks++) {
            int pr = wloc + gid;
            uint32_t af[4];
            af[0] = __float_as_uint(Ps[(pr    ) * KP + ks * 8 + tig    ]);
            af[1] = __float_as_uint(Ps[(pr + 8) * KP + ks * 8 + tig    ]);
            af[2] = __float_as_uint(Ps[(pr    ) * KP + ks * 8 + tig + 4]);
            af[3] = __float_as_uint(Ps[(pr + 8) * KP + ks * 8 + tig + 4]);
            #pragma unroll
            for (int dt = 0; dt < 8; dt++) {
                uint32_t b0 = __float_as_uint(Vs_[(ks * 8 + tig    ) * KP + dt * 8 + gid]);
                uint32_t b1 = __float_as_uint(Vs_[(ks * 8 + tig + 4) * KP + dt * 8 + gid]);
                mma_tf32(oacc[dt], af, b0, b1);
            }
        }

        __syncthreads();  // all warps done with buf before it is refilled
    }

    // normalize + store ctx
    float inv0 = 1.f / l0, inv1 = 1.f / l1;
    #pragma unroll
    for (int dt = 0; dt < 8; dt++) {
        int c = dt * 8 + 2 * tig;
        *(float2*)&ctx[base + (size_t)r0g * EE + c] =
            make_float2(oacc[dt][0] * inv0, oacc[dt][1] * inv0);
        *(float2*)&ctx[base + (size_t)r1g * EE + c] =
            make_float2(oacc[dt][2] * inv1, oacc[dt][3] * inv1);
    }
}

// ---------------------------------------------------------------------------
// Launch
// ---------------------------------------------------------------------------
extern "C" void kernel_launch(void* const* d_in, const int* in_sizes, int n_in,
                              void* d_out, int out_size)
{
    (void)in_sizes; (void)n_in; (void)out_size;
    const float* x  = (const float*)d_in[0];
    const float* Wq = (const float*)d_in[1];
    const float* bq = (const float*)d_in[2];
    const float* Wk = (const float*)d_in[3];
    const float* bk = (const float*)d_in[4];
    const float* Wv = (const float*)d_in[5];
    const float* bv = (const float*)d_in[6];
    const float* Wo = (const float*)d_in[7];
    const float* bo = (const float*)d_in[8];
    float* out = (float*)d_out;

    float *qp, *kp, *vp, *cp;
    cudaGetSymbolAddress((void**)&qp, g_q);
    cudaGetSymbolAddress((void**)&kp, g_k);
    cudaGetSymbolAddress((void**)&vp, g_v);
    cudaGetSymbolAddress((void**)&cp, g_ctx);

    dim3 gqkv(EE / GBN, (BB * SS) / GBM, 3);   // (8, 32, 3)
    sgemm_qkv<<<gqkv, 256>>>(x, Wq, bq, Wk, bk, Wv, bv, qp, kp, vp);

    const int smem = (4 * 64 + 128) * KP * (int)sizeof(float);  // 110592
    cudaFuncSetAttribute(flash_attn_tc, cudaFuncAttributeMaxDynamicSharedMemorySize, smem);
    flash_attn_tc<<<dim3(SS / 128, HH, BB), 256, smem>>>(qp, kp, vp, cp);

    dim3 go(EE / GBN, (BB * SS) / GBM);        // (8, 32)
    sgemm_out<<<go, 256>>>(cp, Wo, bo, out);
}

// round 6
// speedup vs baseline: 1.1429x; 1.0011x over previous
#include <cuda_runtime.h>
#include <math_constants.h>
#include <cstdint>

// Problem constants
#define BB 2
#define SS 2048
#define EE 1024
#define HH 16
#define DD 64

// Scratch (device globals — allocation-free rule)
__device__ float g_q[BB * SS * EE];
__device__ float g_k[BB * SS * EE];
__device__ float g_v[BB * SS * EE];
__device__ float g_ctx[BB * SS * EE];
// tf32 pre-converted inputs
__device__ float g_xt[BB * SS * EE];
__device__ float g_wq[EE * EE];
__device__ float g_wk[EE * EE];
__device__ float g_wv[EE * EE];
__device__ float g_wo[EE * EE];

// ---------------------------------------------------------------------------
// helpers
// ---------------------------------------------------------------------------
__device__ __forceinline__ float f2tf(float f) {
    uint32_t u;
    asm("cvt.rna.tf32.f32 %0, %1;" : "=r"(u) : "f"(f));
    return __uint_as_float(u);
}

__device__ __forceinline__ void mma_tf32(
    float* c, const uint32_t* a, uint32_t b0, uint32_t b1)
{
    asm volatile(
        "mma.sync.aligned.m16n8k8.row.col.f32.tf32.tf32.f32 "
        "{%0,%1,%2,%3},{%4,%5,%6,%7},{%8,%9},{%0,%1,%2,%3};\n"
        : "+f"(c[0]), "+f"(c[1]), "+f"(c[2]), "+f"(c[3])
        : "r"(a[0]), "r"(a[1]), "r"(a[2]), "r"(a[3]), "r"(b0), "r"(b1));
}

__device__ __forceinline__ void cp16(uint32_t smem_dst, const float* gsrc) {
    asm volatile("cp.async.cg.shared.global [%0], [%1], 16;\n"
                 :: "r"(smem_dst), "l"(gsrc));
}
__device__ __forceinline__ void cp_commit() {
    asm volatile("cp.async.commit_group;\n");
}
template<int N>
__device__ __forceinline__ void cp_wait() {
    asm volatile("cp.async.wait_group %0;\n" :: "n"(N));
}

// ---------------------------------------------------------------------------
// tf32 -> tf32 pre-conversion (grid-stride float4)
// ---------------------------------------------------------------------------
__global__ __launch_bounds__(256) void cvt_tf32_k(
    const float* __restrict__ src, float* __restrict__ dst, int n4)
{
    int i = blockIdx.x * blockDim.x + threadIdx.x;
    if (i < n4) {
        float4 v = ((const float4*)src)[i];
        v.x = f2tf(v.x); v.y = f2tf(v.y); v.z = f2tf(v.z); v.w = f2tf(v.w);
        ((float4*)dst)[i] = v;
    }
}

// ---------------------------------------------------------------------------
// tf32 GEMM, inputs pre-converted. C[M,N] = A @ W + bias
// CTA 128x128x16, 128 threads (4 warps, 2x2), warp tile 64x64 (4x8 mma).
// 3-stage cp.async pipeline. A pitch 20, B pitch 136 (both conflict-free).
// mode: 0 = fp32 out, 1 = tf32 out, 2 = tf32 + 0.125 scale
// ---------------------------------------------------------------------------
#define TBK 16
#define AP 20
#define BP 136
#define ASTG (128 * AP)
#define BSTG (TBK * BP)
#define GSMEM (3 * (ASTG + BSTG) * 4)

__device__ __forceinline__ void gemm_body(
    const float* __restrict__ A, const float* __restrict__ W,
    const float* __restrict__ bias, float* __restrict__ C,
    int M, int N, int K, int mode)
{
    extern __shared__ float sh[];
    float* As = sh;                 // [3][128*AP]
    float* Bs = sh + 3 * ASTG;      // [3][TBK*BP]

    const int tid  = threadIdx.x;
    const int lane = tid & 31;
    const int warp = tid >> 5;      // 0..3
    const int gid  = lane >> 2;
    const int tig  = lane & 3;
    const int wm   = warp >> 1;
    const int wn   = warp & 1;
    const int m0   = blockIdx.y * 128;
    const int n0   = blockIdx.x * 128;

    // staging: A one row (16 floats) per thread; B 16 floats per thread
    const int arow = tid;                 // 0..127
    const int bkr  = tid >> 3;            // 0..15
    const int bcl  = (tid & 7) * 16;      // 0..112

    const uint32_t a_base = (uint32_t)__cvta_generic_to_shared(As);
    const uint32_t b_base = (uint32_t)__cvta_generic_to_shared(Bs);

    float acc[4][8][4] = {};

    const int nt = K / TBK;

    // prologue: stages 0,1
    #pragma unroll
    for (int s = 0; s < 2; s++) {
        const float* ag = &A[(size_t)(m0 + arow) * K + s * TBK];
        const float* bg = &W[(size_t)(s * TBK + bkr) * N + n0 + bcl];
        uint32_t ad = a_base + (s * ASTG + arow * AP) * 4;
        uint32_t bd = b_base + (s * BSTG + bkr * BP + bcl) * 4;
        #pragma unroll
        for (int c = 0; c < 4; c++) {
            cp16(ad + c * 16, ag + c * 4);
            cp16(bd + c * 16, bg + c * 4);
        }
        cp_commit();
    }

    for (int kt = 0; kt < nt; kt++) {
        cp_wait<1>();       // stage kt arrived
        __syncthreads();    // all warps see stage kt; all done with stage kt-1

        if (kt + 2 < nt) {
            const int s = (kt + 2) % 3;
            const float* ag = &A[(size_t)(m0 + arow) * K + (kt + 2) * TBK];
            const float* bg = &W[(size_t)((kt + 2) * TBK + bkr) * N + n0 + bcl];
            uint32_t ad = a_base + (s * ASTG + arow * AP) * 4;
            uint32_t bd = b_base + (s * BSTG + bkr * BP + bcl) * 4;
            #pragma unroll
            for (int c = 0; c < 4; c++) {
                cp16(ad + c * 16, ag + c * 4);
                cp16(bd + c * 16, bg + c * 4);
            }
        }
        cp_commit();  // keep group count uniform

        const float* as = &As[(kt % 3) * ASTG];
        const float* bs = &Bs[(kt % 3) * BSTG];

        #pragma unroll
        for (int ks = 0; ks < 2; ks++) {
            uint32_t af[4][4];
            #pragma unroll
            for (int i = 0; i < 4; i++) {
                int mr = wm * 64 + i * 16 + gid;
                af[i][0] = __float_as_uint(as[(mr    ) * AP + ks * 8 + tig    ]);
                af[i][1] = __float_as_uint(as[(mr + 8) * AP + ks * 8 + tig    ]);
                af[i][2] = __float_as_uint(as[(mr    ) * AP + ks * 8 + tig + 4]);
                af[i][3] = __float_as_uint(as[(mr + 8) * AP + ks * 8 + tig + 4]);
            }
            #pragma unroll
            for (int j = 0; j < 8; j++) {
                int nc = wn * 64 + j * 8 + gid;
                uint32_t b0 = __float_as_uint(bs[(ks * 8 + tig    ) * BP + nc]);
                uint32_t b1 = __float_as_uint(bs[(ks * 8 + tig + 4) * BP + nc]);
                #pragma unroll
                for (int i = 0; i < 4; i++)
                    mma_tf32(acc[i][j], af[i], b0, b1);
            }
        }
    }

    // epilogue
    #pragma unroll
    for (int i = 0; i < 4; i++) {
        int r = m0 + wm * 64 + i * 16 + gid;
        #pragma unroll
        for (int j = 0; j < 8; j++) {
            int c = n0 + wn * 64 + j * 8 + 2 * tig;
            float2 bb = *(const float2*)&bias[c];
            float v00 = acc[i][j][0] + bb.x;
            float v01 = acc[i][j][1] + bb.y;
            float v10 = acc[i][j][2] + bb.x;
            float v11 = acc[i][j][3] + bb.y;
            if (mode == 2) { v00 *= 0.125f; v01 *= 0.125f; v10 *= 0.125f; v11 *= 0.125f; }
            if (mode >= 1) { v00 = f2tf(v00); v01 = f2tf(v01); v10 = f2tf(v10); v11 = f2tf(v11); }
            *(float2*)&C[(size_t)r * N + c]       = make_float2(v00, v01);
            *(float2*)&C[(size_t)(r + 8) * N + c] = make_float2(v10, v11);
        }
    }
}

// Merged QKV projection: blockIdx.z selects q/k/v
__global__ __launch_bounds__(128) void sgemm_qkv(
    const float* __restrict__ x,
    const float* __restrict__ Wq, const float* __restrict__ bq,
    const float* __restrict__ Wk, const float* __restrict__ bk,
    const float* __restrict__ Wv, const float* __restrict__ bv,
    float* __restrict__ qp, float* __restrict__ kp, float* __restrict__ vp)
{
    const int z = blockIdx.z;
    const float* W  = (z == 0) ? Wq : (z == 1) ? Wk : Wv;
    const float* bb = (z == 0) ? bq : (z == 1) ? bk : bv;
    float* C        = (z == 0) ? qp : (z == 1) ? kp : vp;
    gemm_body(x, W, bb, C, BB * SS, EE, EE, (z == 0) ? 2 : 1);
}

__global__ __launch_bounds__(128) void sgemm_out(
    const float* __restrict__ A, const float* __restrict__ W,
    const float* __restrict__ bias, float* __restrict__ C)
{
    gemm_body(A, W, bias, C, BB * SS, EE, EE, 0);
}

// ---------------------------------------------------------------------------
// tf32 flash attention, causal. 256 threads = 8 warps.
// Warps 0-3: q rows [q0, q0+64); warps 4-7: [q0+64, q0+128).
// K/V tiles (64 keys x 64 d, pre-tf32) double-buffered via cp.async.
// Writes ctx tf32-rounded (feeds pure-cp.async output GEMM).
// ---------------------------------------------------------------------------
#define KP 72

__global__ __launch_bounds__(256, 2) void flash_attn_tc(
    const float* __restrict__ Qg, const float* __restrict__ Kg,
    const float* __restrict__ Vg, float* __restrict__ ctx)
{
    extern __shared__ float sm[];
    float* Ks0 = sm;
    float* Ks1 = sm + 64 * KP;
    float* Vs0 = sm + 2 * 64 * KP;
    float* Vs1 = sm + 3 * 64 * KP;
    float* Ps  = sm + 4 * 64 * KP;   // [128][KP]

    const int tid  = threadIdx.x;
    const int lane = tid & 31;
    const int warp = tid >> 5;
    const int gid  = lane >> 2;
    const int tig  = lane & 3;
    const int qt2  = (int)gridDim.x - 1 - (int)blockIdx.x;
    const int h    = blockIdx.y;
    const int b    = blockIdx.z;
    const int q0   = qt2 * 128;
    const int wloc = (warp >> 2) * 64 + (warp & 3) * 16;
    const int wbase = q0 + wloc;
    const int nt   = 2 * qt2 + 2;

    const size_t base = (size_t)b * SS * EE + (size_t)h * DD;

    const int srow = tid >> 2;
    const int scol = (tid & 3) * 16;
    const uint32_t ks_dst0 = (uint32_t)__cvta_generic_to_shared(&Ks0[srow * KP + scol]);
    const uint32_t ks_dst1 = (uint32_t)__cvta_generic_to_shared(&Ks1[srow * KP + scol]);
    const uint32_t vs_dst0 = (uint32_t)__cvta_generic_to_shared(&Vs0[srow * KP + scol]);
    const uint32_t vs_dst1 = (uint32_t)__cvta_generic_to_shared(&Vs1[srow * KP + scol]);

    {
        const float* kg = &Kg[base + (size_t)srow * EE + scol];
        const float* vg = &Vg[base + (size_t)srow * EE + scol];
        #pragma unroll
        for (int c = 0; c < 16; c += 4) {
            cp16(ks_dst0 + c * 4, kg + c);
            cp16(vs_dst0 + c * 4, vg + c);
        }
        cp_commit();
    }

    {
        const int qrow = tid >> 1;
        const int qh   = (tid & 1) * 32;
        const float* qsrc = &Qg[base + (size_t)(q0 + qrow) * EE + qh];
        float* d = &Ps[qrow * KP + qh];
        #pragma unroll
        for (int u = 0; u < 8; u++)
            *(float4*)&d[u * 4] = *(const float4*)&qsrc[u * 4];
    }
    __syncthreads();

    uint32_t qf[8][4];
    #pragma unroll
    for (int ks = 0; ks < 8; ks++) {
        int r = wloc + gid;
        qf[ks][0] = __float_as_uint(Ps[(r    ) * KP + ks * 8 + tig    ]);
        qf[ks][1] = __float_as_uint(Ps[(r + 8) * KP + ks * 8 + tig    ]);
        qf[ks][2] = __float_as_uint(Ps[(r    ) * KP + ks * 8 + tig + 4]);
        qf[ks][3] = __float_as_uint(Ps[(r + 8) * KP + ks * 8 + tig + 4]);
    }

    float oacc[8][4] = {};
    float m0r = -CUDART_INF_F, m1r = -CUDART_INF_F;
    float l0 = 0.f, l1 = 0.f;
    const int r0g = wbase + gid;
    const int r1g = r0g + 8;

    for (int kt = 0; kt < nt; kt++) {
        const int k0 = kt * 64;
        const int buf = kt & 1;

        if (kt + 1 < nt) {
            const int kn = (kt + 1) * 64;
            const float* kg = &Kg[base + (size_t)(kn + srow) * EE + scol];
            const float* vg = &Vg[base + (size_t)(kn + srow) * EE + scol];
            const uint32_t kd = buf ? ks_dst0 : ks_dst1;
            const uint32_t vd = buf ? vs_dst0 : vs_dst1;
            #pragma unroll
            for (int c = 0; c < 16; c += 4) {
                cp16(kd + c * 4, kg + c);
                cp16(vd + c * 4, vg + c);
            }
            cp_commit();
            cp_wait<1>();
        } else {
            cp_wait<0>();
        }
        __syncthreads();

        const float* Ks_ = buf ? Ks1 : Ks0;
        const float* Vs_ = buf ? Vs1 : Vs0;

        float sacc[8][4] = {};
        #pragma unroll
        for (int t = 0; t < 8; t++) {
            #pragma unroll
            for (int ks = 0; ks < 8; ks++) {
                uint32_t b0 = __float_as_uint(Ks_[(t * 8 + gid) * KP + ks * 8 + tig    ]);
                uint32_t b1 = __float_as_uint(Ks_[(t * 8 + gid) * KP + ks * 8 + tig + 4]);
                mma_tf32(sacc[t], qf[ks], b0, b1);
            }
        }

        if (k0 + 63 > wbase) {
            #pragma unroll
            for (int t = 0; t < 8; t++) {
                int c = k0 + t * 8 + 2 * tig;
                if (c     > r0g) sacc[t][0] = -CUDART_INF_F;
                if (c + 1 > r0g) sacc[t][1] = -CUDART_INF_F;
                if (c     > r1g) sacc[t][2] = -CUDART_INF_F;
                if (c + 1 > r1g) sacc[t][3] = -CUDART_INF_F;
            }
        }

        float vm0 = -CUDART_INF_F, vm1 = -CUDART_INF_F;
        #pragma unroll
        for (int t = 0; t < 8; t++) {
            vm0 = fmaxf(vm0, fmaxf(sacc[t][0], sacc[t][1]));
            vm1 = fmaxf(vm1, fmaxf(sacc[t][2], sacc[t][3]));
        }
        vm0 = fmaxf(vm0, __shfl_xor_sync(0xffffffffu, vm0, 1));
        vm0 = fmaxf(vm0, __shfl_xor_sync(0xffffffffu, vm0, 2));
        vm1 = fmaxf(vm1, __shfl_xor_sync(0xffffffffu, vm1, 1));
        vm1 = fmaxf(vm1, __shfl_xor_sync(0xffffffffu, vm1, 2));

        float mn0 = fmaxf(m0r, vm0), mn1 = fmaxf(m1r, vm1);
        float al0 = __expf(m0r - mn0), al1 = __expf(m1r - mn1);

        float sum0 = 0.f, sum1 = 0.f;
        #pragma unroll
        for (int t = 0; t < 8; t++) {
            float pv0 = __expf(sacc[t][0] - mn0);
            float pv1 = __expf(sacc[t][1] - mn0);
            float pv2 = __expf(sacc[t][2] - mn1);
            float pv3 = __expf(sacc[t][3] - mn1);
            sacc[t][0] = pv0; sacc[t][1] = pv1; sacc[t][2] = pv2; sacc[t][3] = pv3;
            sum0 += pv0 + pv1;
            sum1 += pv2 + pv3;
        }
        sum0 += __shfl_xor_sync(0xffffffffu, sum0, 1);
        sum0 += __shfl_xor_sync(0xffffffffu, sum0, 2);
        sum1 += __shfl_xor_sync(0xffffffffu, sum1, 1);
        sum1 += __shfl_xor_sync(0xffffffffu, sum1, 2);

        l0 = l0 * al0 + sum0;  m0r = mn0;
        l1 = l1 * al1 + sum1;  m1r = mn1;
        #pragma unroll
        for (int dt = 0; dt < 8; dt++) {
            oacc[dt][0] *= al0; oacc[dt][1] *= al0;
            oacc[dt][2] *= al1; oacc[dt][3] *= al1;
        }

        {
            int pr = wloc + gid;
            #pragma unroll
            for (int t = 0; t < 8; t++) {
                *(float2*)&Ps[(pr    ) * KP + t * 8 + 2 * tig] =
                    make_float2(f2tf(sacc[t][0]), f2tf(sacc[t][1]));
                *(float2*)&Ps[(pr + 8) * KP + t * 8 + 2 * tig] =
                    make_float2(f2tf(sacc[t][2]), f2tf(sacc[t][3]));
            }
        }
        __syncwarp();

        #pragma unroll
        for (int ks = 0; ks < 8; ks++) {
            int pr = wloc + gid;
            uint32_t af[4];
            af[0] = __float_as_uint(Ps[(pr    ) * KP + ks * 8 + tig    ]);
            af[1] = __float_as_uint(Ps[(pr + 8) * KP + ks * 8 + tig    ]);
            af[2] = __float_as_uint(Ps[(pr    ) * KP + ks * 8 + tig + 4]);
            af[3] = __float_as_uint(Ps[(pr + 8) * KP + ks * 8 + tig + 4]);
            #pragma unroll
            for (int dt = 0; dt < 8; dt++) {
                uint32_t b0 = __float_as_uint(Vs_[(ks * 8 + tig    ) * KP + dt * 8 + gid]);
                uint32_t b1 = __float_as_uint(Vs_[(ks * 8 + tig + 4) * KP + dt * 8 + gid]);
                mma_tf32(oacc[dt], af, b0, b1);
            }
        }

        __syncthreads();
    }

    // normalize + store ctx (tf32-rounded for the output GEMM)
    float inv0 = 1.f / l0, inv1 = 1.f / l1;
    #pragma unroll
    for (int dt = 0; dt < 8; dt++) {
        int c = dt * 8 + 2 * tig;
        *(float2*)&ctx[base + (size_t)r0g * EE + c] =
            make_float2(f2tf(oacc[dt][0] * inv0), f2tf(oacc[dt][1] * inv0));
        *(float2*)&ctx[base + (size_t)r1g * EE + c] =
            make_float2(f2tf(oacc[dt][2] * inv1), f2tf(oacc[dt][3] * inv1));
    }
}

// ---------------------------------------------------------------------------
// Launch
// ---------------------------------------------------------------------------
extern "C" void kernel_launch(void* const* d_in, const int* in_sizes, int n_in,
                              void* d_out, int out_size)
{
    (void)in_sizes; (void)n_in; (void)out_size;
    const float* x  = (const float*)d_in[0];
    const float* Wq = (const float*)d_in[1];
    const float* bq = (const float*)d_in[2];
    const float* Wk = (const float*)d_in[3];
    const float* bk = (const float*)d_in[4];
    const float* Wv = (const float*)d_in[5];
    const float* bv = (const float*)d_in[6];
    const float* Wo = (const float*)d_in[7];
    const float* bo = (const float*)d_in[8];
    float* out = (float*)d_out;

    float *qp, *kp, *vp, *cp, *xt, *wq, *wk, *wv, *wo;
    cudaGetSymbolAddress((void**)&qp, g_q);
    cudaGetSymbolAddress((void**)&kp, g_k);
    cudaGetSymbolAddress((void**)&vp, g_v);
    cudaGetSymbolAddress((void**)&cp, g_ctx);
    cudaGetSymbolAddress((void**)&xt, g_xt);
    cudaGetSymbolAddress((void**)&wq, g_wq);
    cudaGetSymbolAddress((void**)&wk, g_wk);
    cudaGetSymbolAddress((void**)&wv, g_wv);
    cudaGetSymbolAddress((void**)&wo, g_wo);

    // pre-convert inputs to tf32
    const int xn4 = BB * SS * EE / 4;   // 1048576
    const int wn4 = EE * EE / 4;        // 262144
    cvt_tf32_k<<<xn4 / 256, 256>>>(x,  xt, xn4);
    cvt_tf32_k<<<wn4 / 256, 256>>>(Wq, wq, wn4);
    cvt_tf32_k<<<wn4 / 256, 256>>>(Wk, wk, wn4);
    cvt_tf32_k<<<wn4 / 256, 256>>>(Wv, wv, wn4);
    cvt_tf32_k<<<wn4 / 256, 256>>>(Wo, wo, wn4);

    cudaFuncSetAttribute(sgemm_qkv, cudaFuncAttributeMaxDynamicSharedMemorySize, GSMEM);
    cudaFuncSetAttribute(sgemm_out, cudaFuncAttributeMaxDynamicSharedMemorySize, GSMEM);

    dim3 gqkv(EE / 128, (BB * SS) / 128, 3);   // (8, 32, 3)
    sgemm_qkv<<<gqkv, 128, GSMEM>>>(xt, wq, bq, wk, bk, wv, bv, qp, kp, vp);

    const int fsmem = (4 * 64 + 128) * KP * (int)sizeof(float);  // 110592
    cudaFuncSetAttribute(flash_attn_tc, cudaFuncAttributeMaxDynamicSharedMemorySize, fsmem);
    flash_attn_tc<<<dim3(SS / 128, HH, BB), 256, fsmem>>>(qp, kp, vp, cp);

    dim3 go(EE / 128, (BB * SS) / 128);        // (8, 32)
    sgemm_out<<<go, 128, GSMEM>>>(cp, wo, bo, out);
}

// round 8
// speedup vs baseline: 2.2706x; 1.9867x over previous
#include <cuda_runtime.h>
#include <cuda_fp16.h>
#include <math_constants.h>
#include <cstdint>

// Problem constants
#define BB 2
#define SS 2048
#define EE 1024
#define HH 16
#define DD 64

// Scratch (device globals — allocation-free rule)
__device__ __half g_q [BB * SS * EE];
__device__ __half g_k [BB * SS * EE];
__device__ __half g_v [BB * SS * EE];
__device__ __half g_vt[BB * HH * DD * SS];   // V transposed: [b][h][d][s]
__device__ __half g_ctx[BB * SS * EE];
__device__ __half g_xt[BB * SS * EE];        // x in fp16
__device__ __half g_wq[EE * EE];             // W^T in fp16: [N][K]
__device__ __half g_wk[EE * EE];
__device__ __half g_wv[EE * EE];
__device__ __half g_wo[EE * EE];

// ---------------------------------------------------------------------------
// helpers
// ---------------------------------------------------------------------------
__device__ __forceinline__ void mma16(
    float* c, const uint32_t* a, uint32_t b0, uint32_t b1)
{
    asm volatile(
        "mma.sync.aligned.m16n8k16.row.col.f32.f16.f16.f32 "
        "{%0,%1,%2,%3},{%4,%5,%6,%7},{%8,%9},{%0,%1,%2,%3};\n"
        : "+f"(c[0]), "+f"(c[1]), "+f"(c[2]), "+f"(c[3])
        : "r"(a[0]), "r"(a[1]), "r"(a[2]), "r"(a[3]), "r"(b0), "r"(b1));
}

__device__ __forceinline__ void cp16(uint32_t smem_dst, const void* gsrc) {
    asm volatile("cp.async.cg.shared.global [%0], [%1], 16;\n"
                 :: "r"(smem_dst), "l"(gsrc));
}
__device__ __forceinline__ void cp_commit() {
    asm volatile("cp.async.commit_group;\n");
}
template<int N>
__device__ __forceinline__ void cp_wait() {
    asm volatile("cp.async.wait_group %0;\n" :: "n"(N));
}

// ---------------------------------------------------------------------------
// fp32 -> fp16 conversion (x)
// ---------------------------------------------------------------------------
__global__ __launch_bounds__(256) void cvt_h(
    const float* __restrict__ src, __half* __restrict__ dst, int n4)
{
    int i = blockIdx.x * blockDim.x + threadIdx.x;
    if (i < n4) {
        float4 v = ((const float4*)src)[i];
        __half2 h0 = __floats2half2_rn(v.x, v.y);
        __half2 h1 = __floats2half2_rn(v.z, v.w);
        *(uint2*)&dst[4 * i] = make_uint2(
            *(uint32_t*)&h0, *(uint32_t*)&h1);
    }
}

// fp32 W[K][N] -> fp16 W^T[N][K]
__global__ __launch_bounds__(256) void transcvt_w(
    const float* __restrict__ W, __half* __restrict__ Wt)
{
    __shared__ float t[32][33];
    const int n0 = blockIdx.x * 32;
    const int k0 = blockIdx.y * 32;
    const int tx = threadIdx.x;
    const int ty = threadIdx.y;
    #pragma unroll
    for (int i = 0; i < 32; i += 8)
        t[ty + i][tx] = W[(size_t)(k0 + ty + i) * EE + n0 + tx];
    __syncthreads();
    #pragma unroll
    for (int i = 0; i < 32; i += 8)
        Wt[(size_t)(n0 + ty + i) * EE + k0 + tx] = __float2half(t[tx][ty + i]);
}

// v[b][s][h*64+d] (fp16) -> vt[b][h][d][s] (fp16)
__global__ __launch_bounds__(256) void trans_v(
    const __half* __restrict__ v, __half* __restrict__ vt)
{
    __shared__ __half t[32][33];
    const int s0 = blockIdx.x * 32;
    const int h  = blockIdx.y >> 1;
    const int d0 = (blockIdx.y & 1) * 32;
    const int b  = blockIdx.z;
    const int tx = threadIdx.x;
    const int ty = threadIdx.y;
    #pragma unroll
    for (int i = 0; i < 32; i += 8)
        t[ty + i][tx] = v[((size_t)b * SS + s0 + ty + i) * EE + h * DD + d0 + tx];
    __syncthreads();
    #pragma unroll
    for (int i = 0; i < 32; i += 8)
        vt[(((size_t)b * HH + h) * DD + d0 + ty + i) * SS + s0 + tx] = t[tx][ty + i];
}

// ---------------------------------------------------------------------------
// fp16 GEMM: C[4096,1024] = A[4096,1024] @ W + bias, W given as W^T fp16.
// CTA 128x128, 128 threads (4 warps 2x2), warp tile 64x64, BK=32 halves,
// 3-stage cp.async. Pitch 40 halves (80B): banks (20*gid+tig) distinct.
// mode: 0 = fp32 out, 1 = fp16 out, 2 = fp16 out * 0.125
// ---------------------------------------------------------------------------
#define HBK 32
#define HAP 40
#define HSTG (128 * HAP)
#define HSMEM (3 * 2 * HSTG * 2)   // 61440 bytes

__device__ __forceinline__ void gemm16_body(
    const __half* __restrict__ A, const __half* __restrict__ Wt,
    const float* __restrict__ bias, void* Cv, int mode)
{
    extern __shared__ __half hsm[];
    __half* As = hsm;                // [3][HSTG]
    __half* Bs = hsm + 3 * HSTG;

    const int tid  = threadIdx.x;
    const int lane = tid & 31;
    const int warp = tid >> 5;
    const int gid  = lane >> 2;
    const int tig  = lane & 3;
    const int wm   = warp >> 1;
    const int wn   = warp & 1;
    const int m0   = blockIdx.y * 128;
    const int n0   = blockIdx.x * 128;

    const uint32_t a_base = (uint32_t)__cvta_generic_to_shared(As);
    const uint32_t b_base = (uint32_t)__cvta_generic_to_shared(Bs);

    float acc[4][8][4] = {};
    const int nt = EE / HBK;  // 32

    // prologue: stages 0, 1
    #pragma unroll
    for (int s = 0; s < 2; s++) {
        const __half* ag = &A [(size_t)(m0 + tid) * EE + s * HBK];
        const __half* bg = &Wt[(size_t)(n0 + tid) * EE + s * HBK];
        uint32_t ad = a_base + (s * HSTG + tid * HAP) * 2;
        uint32_t bd = b_base + (s * HSTG + tid * HAP) * 2;
        #pragma unroll
        for (int c = 0; c < 4; c++) {
            cp16(ad + c * 16, ag + c * 8);
            cp16(bd + c * 16, bg + c * 8);
        }
        cp_commit();
    }

    for (int kt = 0; kt < nt; kt++) {
        cp_wait<1>();
        __syncthreads();

        if (kt + 2 < nt) {
            const int s = (kt + 2) % 3;
            const __half* ag = &A [(size_t)(m0 + tid) * EE + (kt + 2) * HBK];
            const __half* bg = &Wt[(size_t)(n0 + tid) * EE + (kt + 2) * HBK];
            uint32_t ad = a_base + (s * HSTG + tid * HAP) * 2;
            uint32_t bd = b_base + (s * HSTG + tid * HAP) * 2;
            #pragma unroll
            for (int c = 0; c < 4; c++) {
                cp16(ad + c * 16, ag + c * 8);
                cp16(bd + c * 16, bg + c * 8);
            }
        }
        cp_commit();

        const __half* as = &As[(kt % 3) * HSTG];
        const __half* bs = &Bs[(kt % 3) * HSTG];

        #pragma unroll
        for (int ks = 0; ks < 2; ks++) {
            uint32_t af[4][4];
            #pragma unroll
            for (int i = 0; i < 4; i++) {
                int mr = wm * 64 + i * 16 + gid;
                af[i][0] = *(const uint32_t*)&as[(mr    ) * HAP + ks * 16 + 2 * tig];
                af[i][1] = *(const uint32_t*)&as[(mr + 8) * HAP + ks * 16 + 2 * tig];
                af[i][2] = *(const uint32_t*)&as[(mr    ) * HAP + ks * 16 + 8 + 2 * tig];
                af[i][3] = *(const uint32_t*)&as[(mr + 8) * HAP + ks * 16 + 8 + 2 * tig];
            }
            #pragma unroll
            for (int j = 0; j < 8; j++) {
                int nc = wn * 64 + j * 8 + gid;
                uint32_t b0 = *(const uint32_t*)&bs[nc * HAP + ks * 16 + 2 * tig];
                uint32_t b1 = *(const uint32_t*)&bs[nc * HAP + ks * 16 + 8 + 2 * tig];
                #pragma unroll
                for (int i = 0; i < 4; i++)
                    mma16(acc[i][j], af[i], b0, b1);
            }
        }
    }

    // epilogue
    #pragma unroll
    for (int i = 0; i < 4; i++) {
        int r = m0 + wm * 64 + i * 16 + gid;
        #pragma unroll
        for (int j = 0; j < 8; j++) {
            int c = n0 + wn * 64 + j * 8 + 2 * tig;
            float2 bb = *(const float2*)&bias[c];
            float v00 = acc[i][j][0] + bb.x;
            float v01 = acc[i][j][1] + bb.y;
            float v10 = acc[i][j][2] + bb.x;
            float v11 = acc[i][j][3] + bb.y;
            if (mode == 0) {
                float* C = (float*)Cv;
                *(float2*)&C[(size_t)r * EE + c]       = make_float2(v00, v01);
                *(float2*)&C[(size_t)(r + 8) * EE + c] = make_float2(v10, v11);
            } else {
                if (mode == 2) { v00 *= 0.125f; v01 *= 0.125f; v10 *= 0.125f; v11 *= 0.125f; }
                __half* C = (__half*)Cv;
                *(__half2*)&C[(size_t)r * EE + c]       = __floats2half2_rn(v00, v01);
                *(__half2*)&C[(size_t)(r + 8) * EE + c] = __floats2half2_rn(v10, v11);
            }
        }
    }
}

__global__ __launch_bounds__(128) void gemm16_qkv(
    const __half* __restrict__ x,
    const __half* __restrict__ Wq, const float* __restrict__ bq,
    const __half* __restrict__ Wk, const float* __restrict__ bk,
    const __half* __restrict__ Wv, const float* __restrict__ bv,
    __half* __restrict__ qp, __half* __restrict__ kp, __half* __restrict__ vp)
{
    const int z = blockIdx.z;
    const __half* W  = (z == 0) ? Wq : (z == 1) ? Wk : Wv;
    const float* bb  = (z == 0) ? bq : (z == 1) ? bk : bv;
    __half* C        = (z == 0) ? qp : (z == 1) ? kp : vp;
    gemm16_body(x, W, bb, C, (z == 0) ? 2 : 1);
}

__global__ __launch_bounds__(128) void gemm16_out(
    const __half* __restrict__ A, const __half* __restrict__ Wt,
    const float* __restrict__ bias, float* __restrict__ C)
{
    gemm16_body(A, Wt, bias, C, 0);
}

// ---------------------------------------------------------------------------
// fp16 flash attention, causal. 256 threads = 8 warps.
// Warps 0-3: rows [q0,q0+64); warps 4-7: [q0+64,q0+128).
// K natural [key][d] (= B layout for QK^T), V pre-transposed [d][key].
// Double-buffered via cp.async. Pitch 72 halves (144B: 36≡4 mod 32 banks).
// ---------------------------------------------------------------------------
#define KPH 72
#define FSMEM ((4 * 64 + 128) * KPH * 2)   // 55296 bytes

__global__ __launch_bounds__(256, 2) void flash16(
    const __half* __restrict__ Qg, const __half* __restrict__ Kg,
    const __half* __restrict__ Vtg, __half* __restrict__ ctx)
{
    extern __shared__ __half fsm[];
    __half* Ks0 = fsm;
    __half* Ks1 = fsm + 64 * KPH;
    __half* Vt0 = fsm + 2 * 64 * KPH;
    __half* Vt1 = fsm + 3 * 64 * KPH;
    __half* Ps  = fsm + 4 * 64 * KPH;   // [128][KPH]

    const int tid  = threadIdx.x;
    const int lane = tid & 31;
    const int warp = tid >> 5;
    const int gid  = lane >> 2;
    const int tig  = lane & 3;
    const int qt2  = (int)gridDim.x - 1 - (int)blockIdx.x;  // heavy first
    const int h    = blockIdx.y;
    const int b    = blockIdx.z;
    const int q0   = qt2 * 128;
    const int wloc = (warp >> 2) * 64 + (warp & 3) * 16;
    const int wbase = q0 + wloc;
    const int nt   = 2 * qt2 + 2;

    const size_t base  = (size_t)b * SS * EE + (size_t)h * DD;       // q/k/ctx
    const size_t vbase = ((size_t)b * HH + h) * DD * SS;             // vt

    // staging: K tile 64key x 64d halves; Vt tile 64d x 64key halves
    const int srow = tid >> 2;           // 0..63
    const int scol = (tid & 3) * 16;     // halves (32B = 2 cp16)
    const uint32_t k_d0 = (uint32_t)__cvta_generic_to_shared(&Ks0[srow * KPH + scol]);
    const uint32_t k_d1 = (uint32_t)__cvta_generic_to_shared(&Ks1[srow * KPH + scol]);
    const uint32_t v_d0 = (uint32_t)__cvta_generic_to_shared(&Vt0[srow * KPH + scol]);
    const uint32_t v_d1 = (uint32_t)__cvta_generic_to_shared(&Vt1[srow * KPH + scol]);

    // group 1: Q tile (into Ps): 128 rows x 64 halves
    {
        const int qrow = tid >> 1;
        const int qh   = (tid & 1) * 32;
        const __half* qsrc = &Qg[base + (size_t)(q0 + qrow) * EE + qh];
        uint32_t qd = (uint32_t)__cvta_generic_to_shared(&Ps[qrow * KPH + qh]);
        #pragma unroll
        for (int c = 0; c < 4; c++)
            cp16(qd + c * 16, qsrc + c * 8);
        cp_commit();
    }
    // group 2: K/V tile 0
    {
        const __half* kg = &Kg [base  + (size_t)srow * EE + scol];
        const __half* vg = &Vtg[vbase + (size_t)srow * SS + scol];
        cp16(k_d0,      kg);     cp16(k_d0 + 16, kg + 8);
        cp16(v_d0,      vg);     cp16(v_d0 + 16, vg + 8);
        cp_commit();
    }
    cp_wait<1>();      // Q arrived (K/V tile0 may be in flight)
    __syncthreads();

    uint32_t qf[4][4];
    #pragma unroll
    for (int ks = 0; ks < 4; ks++) {
        int r = wloc + gid;
        qf[ks][0] = *(const uint32_t*)&Ps[(r    ) * KPH + ks * 16 + 2 * tig];
        qf[ks][1] = *(const uint32_t*)&Ps[(r + 8) * KPH + ks * 16 + 2 * tig];
        qf[ks][2] = *(const uint32_t*)&Ps[(r    ) * KPH + ks * 16 + 8 + 2 * tig];
        qf[ks][3] = *(const uint32_t*)&Ps[(r + 8) * KPH + ks * 16 + 8 + 2 * tig];
    }

    float oacc[8][4] = {};
    float m0r = -CUDART_INF_F, m1r = -CUDART_INF_F;
    float l0 = 0.f, l1 = 0.f;
    const int r0g = wbase + gid;
    const int r1g = r0g + 8;

    for (int kt = 0; kt < nt; kt++) {
        const int k0 = kt * 64;
        const int buf = kt & 1;

        if (kt + 1 < nt) {
            const int kn = (kt + 1) * 64;
            const __half* kg = &Kg [base  + (size_t)(kn + srow) * EE + scol];
            const __half* vg = &Vtg[vbase + (size_t)srow * SS + kn + scol];
            const uint32_t kd = buf ? k_d0 : k_d1;
            const uint32_t vd = buf ? v_d0 : v_d1;
            cp16(kd,      kg);     cp16(kd + 16, kg + 8);
            cp16(vd,      vg);     cp16(vd + 16, vg + 8);
            cp_commit();
            cp_wait<1>();
        } else {
            cp_wait<0>();
        }
        __syncthreads();

        const __half* Ks_ = buf ? Ks1 : Ks0;
        const __half* Vt_ = buf ? Vt1 : Vt0;

        // S = Q @ K^T
        float sacc[8][4] = {};
        #pragma unroll
        for (int t = 0; t < 8; t++) {
            #pragma unroll
            for (int ks = 0; ks < 4; ks++) {
                uint32_t b0 = *(const uint32_t*)&Ks_[(t * 8 + gid) * KPH + ks * 16 + 2 * tig];
                uint32_t b1 = *(const uint32_t*)&Ks_[(t * 8 + gid) * KPH + ks * 16 + 8 + 2 * tig];
                mma16(sacc[t], qf[ks], b0, b1);
            }
        }

        // causal mask (only tiles crossing the diagonal of this warp's rows)
        if (k0 + 63 > wbase) {
            #pragma unroll
            for (int t = 0; t < 8; t++) {
                int c = k0 + t * 8 + 2 * tig;
                if (c     > r0g) sacc[t][0] = -CUDART_INF_F;
                if (c + 1 > r0g) sacc[t][1] = -CUDART_INF_F;
                if (c     > r1g) sacc[t][2] = -CUDART_INF_F;
                if (c + 1 > r1g) sacc[t][3] = -CUDART_INF_F;
            }
        }

        // online softmax
        float vm0 = -CUDART_INF_F, vm1 = -CUDART_INF_F;
        #pragma unroll
        for (int t = 0; t < 8; t++) {
            vm0 = fmaxf(vm0, fmaxf(sacc[t][0], sacc[t][1]));
            vm1 = fmaxf(vm1, fmaxf(sacc[t][2], sacc[t][3]));
        }
        vm0 = fmaxf(vm0, __shfl_xor_sync(0xffffffffu, vm0, 1));
        vm0 = fmaxf(vm0, __shfl_xor_sync(0xffffffffu, vm0, 2));
        vm1 = fmaxf(vm1, __shfl_xor_sync(0xffffffffu, vm1, 1));
        vm1 = fmaxf(vm1, __shfl_xor_sync(0xffffffffu, vm1, 2));

        float mn0 = fmaxf(m0r, vm0), mn1 = fmaxf(m1r, vm1);
        float al0 = __expf(m0r - mn0), al1 = __expf(m1r - mn1);

        float sum0 = 0.f, sum1 = 0.f;
        #pragma unroll
        for (int t = 0; t < 8; t++) {
            float p0 = __expf(sacc[t][0] - mn0);
            float p1 = __expf(sacc[t][1] - mn0);
            float p2 = __expf(sacc[t][2] - mn1);
            float p3 = __expf(sacc[t][3] - mn1);
            sacc[t][0] = p0; sacc[t][1] = p1; sacc[t][2] = p2; sacc[t][3] = p3;
            sum0 += p0 + p1;
            sum1 += p2 + p3;
        }
        sum0 += __shfl_xor_sync(0xffffffffu, sum0, 1);
        sum0 += __shfl_xor_sync(0xffffffffu, sum0, 2);
        sum1 += __shfl_xor_sync(0xffffffffu, sum1, 1);
        sum1 += __shfl_xor_sync(0xffffffffu, sum1, 2);

        l0 = l0 * al0 + sum0;  m0r = mn0;
        l1 = l1 * al1 + sum1;  m1r = mn1;
        #pragma unroll
        for (int dt = 0; dt < 8; dt++) {
            oacc[dt][0] *= al0; oacc[dt][1] *= al0;
            oacc[dt][2] *= al1; oacc[dt][3] *= al1;
        }

        // stage P as half2 pairs into own rows (warp-local)
        {
            int pr = wloc + gid;
            #pragma unroll
            for (int t = 0; t < 8; t++) {
                *(__half2*)&Ps[(pr    ) * KPH + t * 8 + 2 * tig] =
                    __floats2half2_rn(sacc[t][0], sacc[t][1]);
                *(__half2*)&Ps[(pr + 8) * KPH + t * 8 + 2 * tig] =
                    __floats2half2_rn(sacc[t][2], sacc[t][3]);
            }
        }
        __syncwarp();

        // O += P @ V
        #pragma unroll
        for (int ks = 0; ks < 4; ks++) {
            int pr = wloc + gid;
            uint32_t af[4];
            af[0] = *(const uint32_t*)&Ps[(pr    ) * KPH + ks * 16 + 2 * tig];
            af[1] = *(const uint32_t*)&Ps[(pr + 8) * KPH + ks * 16 + 2 * tig];
            af[2] = *(const uint32_t*)&Ps[(pr    ) * KPH + ks * 16 + 8 + 2 * tig];
            af[3] = *(const uint32_t*)&Ps[(pr + 8) * KPH + ks * 16 + 8 + 2 * tig];
            #pragma unroll
            for (int dt = 0; dt < 8; dt++) {
                uint32_t b0 = *(const uint32_t*)&Vt_[(dt * 8 + gid) * KPH + ks * 16 + 2 * tig];
                uint32_t b1 = *(const uint32_t*)&Vt_[(dt * 8 + gid) * KPH + ks * 16 + 8 + 2 * tig];
                mma16(oacc[dt], af, b0, b1);
            }
        }

        __syncthreads();
    }

    // normalize + store ctx (fp16)
    float inv0 = 1.f / l0, inv1 = 1.f / l1;
    #pragma unroll
    for (int dt = 0; dt < 8; dt++) {
        int c = dt * 8 + 2 * tig;
        *(__half2*)&ctx[base + (size_t)r0g * EE + c] =
            __floats2half2_rn(oacc[dt][0] * inv0, oacc[dt][1] * inv0);
        *(__half2*)&ctx[base + (size_t)r1g * EE + c] =
            __floats2half2_rn(oacc[dt][2] * inv1, oacc[dt][3] * inv1);
    }
}

// ---------------------------------------------------------------------------
// Launch
// ---------------------------------------------------------------------------
extern "C" void kernel_launch(void* const* d_in, const int* in_sizes, int n_in,
                              void* d_out, int out_size)
{
    (void)in_sizes; (void)n_in; (void)out_size;
    const float* x  = (const float*)d_in[0];
    const float* Wq = (const float*)d_in[1];
    const float* bq = (const float*)d_in[2];
    const float* Wk = (const float*)d_in[3];
    const float* bk = (const float*)d_in[4];
    const float* Wv = (const float*)d_in[5];
    const float* bv = (const float*)d_in[6];
    const float* Wo = (const float*)d_in[7];
    const float* bo = (const float*)d_in[8];
    float* out = (float*)d_out;

    __half *qp, *kp, *vp, *vtp, *cp, *xt, *wq, *wk, *wv, *wo;
    cudaGetSymbolAddress((void**)&qp,  g_q);
    cudaGetSymbolAddress((void**)&kp,  g_k);
    cudaGetSymbolAddress((void**)&vp,  g_v);
    cudaGetSymbolAddress((void**)&vtp, g_vt);
    cudaGetSymbolAddress((void**)&cp,  g_ctx);
    cudaGetSymbolAddress((void**)&xt,  g_xt);
    cudaGetSymbolAddress((void**)&wq,  g_wq);
    cudaGetSymbolAddress((void**)&wk,  g_wk);
    cudaGetSymbolAddress((void**)&wv,  g_wv);
    cudaGetSymbolAddress((void**)&wo,  g_wo);

    // prologue conversions
    const int xn4 = BB * SS * EE / 4;
    cvt_h<<<xn4 / 256, 256>>>(x, xt, xn4);
    dim3 tb(32, 8), tg(EE / 32, EE / 32);
    transcvt_w<<<tg, tb>>>(Wq, wq);
    transcvt_w<<<tg, tb>>>(Wk, wk);
    transcvt_w<<<tg, tb>>>(Wv, wv);
    transcvt_w<<<tg, tb>>>(Wo, wo);

    cudaFuncSetAttribute(gemm16_qkv, cudaFuncAttributeMaxDynamicSharedMemorySize, HSMEM);
    cudaFuncSetAttribute(gemm16_out, cudaFuncAttributeMaxDynamicSharedMemorySize, HSMEM);
    cudaFuncSetAttribute(flash16, cudaFuncAttributeMaxDynamicSharedMemorySize, FSMEM);

    dim3 gqkv(EE / 128, (BB * SS) / 128, 3);
    gemm16_qkv<<<gqkv, 128, HSMEM>>>(xt, wq, bq, wk, bk, wv, bv, qp, kp, vp);

    trans_v<<<dim3(SS / 32, 2 * HH, BB), tb>>>(vp, vtp);

    flash16<<<dim3(SS / 128, HH, BB), 256, FSMEM>>>(qp, kp, vtp, cp);

    dim3 go(EE / 128, (BB * SS) / 128);
    gemm16_out<<<go, 128, HSMEM>>>(cp, wo, bo, out);
}

// round 9
// speedup vs baseline: 2.4092x; 1.0610x over previous
#include <cuda_runtime.h>
#include <cuda_fp16.h>
#include <math_constants.h>
#include <cstdint>

// Problem constants
#define BB 2
#define SS 2048
#define EE 1024
#define HH 16
#define DD 64

// Scratch (device globals — allocation-free rule)
__device__ __half g_q [BB * SS * EE];
__device__ __half g_k [BB * SS * EE];
__device__ __half g_v [BB * SS * EE];
__device__ __half g_vt[BB * HH * DD * SS];   // V transposed: [b][h][d][s]
__device__ __half g_ctx[BB * SS * EE];
__device__ __half g_xt[BB * SS * EE];        // x in fp16
__device__ __half g_wq[EE * EE];             // W^T in fp16: [N][K]
__device__ __half g_wk[EE * EE];
__device__ __half g_wv[EE * EE];
__device__ __half g_wo[EE * EE];

// ---------------------------------------------------------------------------
// helpers
// ---------------------------------------------------------------------------
__device__ __forceinline__ void mma16(
    float* c, const uint32_t* a, uint32_t b0, uint32_t b1)
{
    asm volatile(
        "mma.sync.aligned.m16n8k16.row.col.f32.f16.f16.f32 "
        "{%0,%1,%2,%3},{%4,%5,%6,%7},{%8,%9},{%0,%1,%2,%3};\n"
        : "+f"(c[0]), "+f"(c[1]), "+f"(c[2]), "+f"(c[3])
        : "r"(a[0]), "r"(a[1]), "r"(a[2]), "r"(a[3]), "r"(b0), "r"(b1));
}

__device__ __forceinline__ uint32_t packh2(float a, float b) {
    __half2 h = __floats2half2_rn(a, b);
    return *(uint32_t*)&h;
}

__device__ __forceinline__ void cp16(uint32_t smem_dst, const void* gsrc) {
    asm volatile("cp.async.cg.shared.global [%0], [%1], 16;\n"
                 :: "r"(smem_dst), "l"(gsrc));
}
__device__ __forceinline__ void cp_commit() {
    asm volatile("cp.async.commit_group;\n");
}
template<int N>
__device__ __forceinline__ void cp_wait() {
    asm volatile("cp.async.wait_group %0;\n" :: "n"(N));
}

// ---------------------------------------------------------------------------
// prologue conversions
// ---------------------------------------------------------------------------
__global__ __launch_bounds__(256) void cvt_h(
    const float* __restrict__ src, __half* __restrict__ dst, int n4)
{
    int i = blockIdx.x * blockDim.x + threadIdx.x;
    if (i < n4) {
        float4 v = ((const float4*)src)[i];
        __half2 h0 = __floats2half2_rn(v.x, v.y);
        __half2 h1 = __floats2half2_rn(v.z, v.w);
        *(uint2*)&dst[4 * i] = make_uint2(*(uint32_t*)&h0, *(uint32_t*)&h1);
    }
}

// fp32 W[K][N] -> fp16 W^T[N][K], 4 weights in one launch (z selects)
__global__ __launch_bounds__(256) void transcvt_w4(
    const float* __restrict__ W0, const float* __restrict__ W1,
    const float* __restrict__ W2, const float* __restrict__ W3,
    __half* __restrict__ T0, __half* __restrict__ T1,
    __half* __restrict__ T2, __half* __restrict__ T3)
{
    const int z = blockIdx.z;
    const float* W = (z == 0) ? W0 : (z == 1) ? W1 : (z == 2) ? W2 : W3;
    __half* Wt     = (z == 0) ? T0 : (z == 1) ? T1 : (z == 2) ? T2 : T3;

    __shared__ float t[32][33];
    const int n0 = blockIdx.x * 32;
    const int k0 = blockIdx.y * 32;
    const int tx = threadIdx.x;
    const int ty = threadIdx.y;
    #pragma unroll
    for (int i = 0; i < 32; i += 8)
        t[ty + i][tx] = W[(size_t)(k0 + ty + i) * EE + n0 + tx];
    __syncthreads();
    #pragma unroll
    for (int i = 0; i < 32; i += 8)
        Wt[(size_t)(n0 + ty + i) * EE + k0 + tx] = __float2half(t[tx][ty + i]);
}

// v[b][s][h*64+d] (fp16) -> vt[b][h][d][s] (fp16)
__global__ __launch_bounds__(256) void trans_v(
    const __half* __restrict__ v, __half* __restrict__ vt)
{
    __shared__ __half t[32][33];
    const int s0 = blockIdx.x * 32;
    const int h  = blockIdx.y >> 1;
    const int d0 = (blockIdx.y & 1) * 32;
    const int b  = blockIdx.z;
    const int tx = threadIdx.x;
    const int ty = threadIdx.y;
    #pragma unroll
    for (int i = 0; i < 32; i += 8)
        t[ty + i][tx] = v[((size_t)b * SS + s0 + ty + i) * EE + h * DD + d0 + tx];
    __syncthreads();
    #pragma unroll
    for (int i = 0; i < 32; i += 8)
        vt[(((size_t)b * HH + h) * DD + d0 + ty + i) * SS + s0 + tx] = t[tx][ty + i];
}

// ---------------------------------------------------------------------------
// fp16 GEMM: C[4096,1024] = A @ W + bias, W given as W^T fp16.
// CTA 128x128, 128 threads (4 warps 2x2), warp tile 64x64, BK=32 halves,
// 3-stage cp.async. Pitch 40 halves.
// mode: 0 = fp32 out, 1 = fp16 out, 2 = fp16 out * 0.125
// ---------------------------------------------------------------------------
#define HBK 32
#define HAP 40
#define HSTG (128 * HAP)
#define HSMEM (3 * 2 * HSTG * 2)   // 61440 bytes

__device__ __forceinline__ void gemm16_body(
    const __half* __restrict__ A, const __half* __restrict__ Wt,
    const float* __restrict__ bias, void* Cv, int mode)
{
    extern __shared__ __half hsm[];
    __half* As = hsm;
    __half* Bs = hsm + 3 * HSTG;

    const int tid  = threadIdx.x;
    const int lane = tid & 31;
    const int warp = tid >> 5;
    const int gid  = lane >> 2;
    const int tig  = lane & 3;
    const int wm   = warp >> 1;
    const int wn   = warp & 1;
    const int m0   = blockIdx.y * 128;
    const int n0   = blockIdx.x * 128;

    const uint32_t a_base = (uint32_t)__cvta_generic_to_shared(As);
    const uint32_t b_base = (uint32_t)__cvta_generic_to_shared(Bs);

    float acc[4][8][4] = {};
    const int nt = EE / HBK;

    #pragma unroll
    for (int s = 0; s < 2; s++) {
        const __half* ag = &A [(size_t)(m0 + tid) * EE + s * HBK];
        const __half* bg = &Wt[(size_t)(n0 + tid) * EE + s * HBK];
        uint32_t ad = a_base + (s * HSTG + tid * HAP) * 2;
        uint32_t bd = b_base + (s * HSTG + tid * HAP) * 2;
        #pragma unroll
        for (int c = 0; c < 4; c++) {
            cp16(ad + c * 16, ag + c * 8);
            cp16(bd + c * 16, bg + c * 8);
        }
        cp_commit();
    }

    for (int kt = 0; kt < nt; kt++) {
        cp_wait<1>();
        __syncthreads();

        if (kt + 2 < nt) {
            const int s = (kt + 2) % 3;
            const __half* ag = &A [(size_t)(m0 + tid) * EE + (kt + 2) * HBK];
            const __half* bg = &Wt[(size_t)(n0 + tid) * EE + (kt + 2) * HBK];
            uint32_t ad = a_base + (s * HSTG + tid * HAP) * 2;
            uint32_t bd = b_base + (s * HSTG + tid * HAP) * 2;
            #pragma unroll
            for (int c = 0; c < 4; c++) {
                cp16(ad + c * 16, ag + c * 8);
                cp16(bd + c * 16, bg + c * 8);
            }
        }
        cp_commit();

        const __half* as = &As[(kt % 3) * HSTG];
        const __half* bs = &Bs[(kt % 3) * HSTG];

        #pragma unroll
        for (int ks = 0; ks < 2; ks++) {
            uint32_t af[4][4];
            #pragma unroll
            for (int i = 0; i < 4; i++) {
                int mr = wm * 64 + i * 16 + gid;
                af[i][0] = *(const uint32_t*)&as[(mr    ) * HAP + ks * 16 + 2 * tig];
                af[i][1] = *(const uint32_t*)&as[(mr + 8) * HAP + ks * 16 + 2 * tig];
                af[i][2] = *(const uint32_t*)&as[(mr    ) * HAP + ks * 16 + 8 + 2 * tig];
                af[i][3] = *(const uint32_t*)&as[(mr + 8) * HAP + ks * 16 + 8 + 2 * tig];
            }
            #pragma unroll
            for (int j = 0; j < 8; j++) {
                int nc = wn * 64 + j * 8 + gid;
                uint32_t b0 = *(const uint32_t*)&bs[nc * HAP + ks * 16 + 2 * tig];
                uint32_t b1 = *(const uint32_t*)&bs[nc * HAP + ks * 16 + 8 + 2 * tig];
                #pragma unroll
                for (int i = 0; i < 4; i++)
                    mma16(acc[i][j], af[i], b0, b1);
            }
        }
    }

    #pragma unroll
    for (int i = 0; i < 4; i++) {
        int r = m0 + wm * 64 + i * 16 + gid;
        #pragma unroll
        for (int j = 0; j < 8; j++) {
            int c = n0 + wn * 64 + j * 8 + 2 * tig;
            float2 bb = *(const float2*)&bias[c];
            float v00 = acc[i][j][0] + bb.x;
            float v01 = acc[i][j][1] + bb.y;
            float v10 = acc[i][j][2] + bb.x;
            float v11 = acc[i][j][3] + bb.y;
            if (mode == 0) {
                float* C = (float*)Cv;
                *(float2*)&C[(size_t)r * EE + c]       = make_float2(v00, v01);
                *(float2*)&C[(size_t)(r + 8) * EE + c] = make_float2(v10, v11);
            } else {
                if (mode == 2) { v00 *= 0.125f; v01 *= 0.125f; v10 *= 0.125f; v11 *= 0.125f; }
                __half* C = (__half*)Cv;
                *(__half2*)&C[(size_t)r * EE + c]       = __floats2half2_rn(v00, v01);
                *(__half2*)&C[(size_t)(r + 8) * EE + c] = __floats2half2_rn(v10, v11);
            }
        }
    }
}

__global__ __launch_bounds__(128) void gemm16_qkv(
    const __half* __restrict__ x,
    const __half* __restrict__ Wq, const float* __restrict__ bq,
    const __half* __restrict__ Wk, const float* __restrict__ bk,
    const __half* __restrict__ Wv, const float* __restrict__ bv,
    __half* __restrict__ qp, __half* __restrict__ kp, __half* __restrict__ vp)
{
    const int z = blockIdx.z;
    const __half* W  = (z == 0) ? Wq : (z == 1) ? Wk : Wv;
    const float* bb  = (z == 0) ? bq : (z == 1) ? bk : bv;
    __half* C        = (z == 0) ? qp : (z == 1) ? kp : vp;
    gemm16_body(x, W, bb, C, (z == 0) ? 2 : 1);
}

__global__ __launch_bounds__(128) void gemm16_out(
    const __half* __restrict__ A, const __half* __restrict__ Wt,
    const float* __restrict__ bias, float* __restrict__ C)
{
    gemm16_body(A, Wt, bias, C, 0);
}

// ---------------------------------------------------------------------------
// fp16 flash attention, causal. 256 threads = 8 warps.
// Warps 0-3: rows [q0,q0+64); warps 4-7: [q0+64,q0+128).
// P stays in registers: QK C-fragments repack directly into PV A-fragments
// (identical thread mapping). No P smem, no syncwarp.
// smem: Ks0,Ks1,Vt0,Vt1 [64][72] halves = 36864 B. Q staged via Ks region.
// ---------------------------------------------------------------------------
#define KPH 72
#define FSMEM (4 * 64 * KPH * 2)   // 36864 bytes

__global__ __launch_bounds__(256, 2) void flash16(
    const __half* __restrict__ Qg, const __half* __restrict__ Kg,
    const __half* __restrict__ Vtg, __half* __restrict__ ctx)
{
    extern __shared__ __half fsm[];
    __half* Ks0 = fsm;
    __half* Ks1 = fsm + 64 * KPH;
    __half* Vt0 = fsm + 2 * 64 * KPH;
    __half* Vt1 = fsm + 3 * 64 * KPH;

    const int tid  = threadIdx.x;
    const int lane = tid & 31;
    const int warp = tid >> 5;
    const int gid  = lane >> 2;
    const int tig  = lane & 3;
    const int qt2  = (int)gridDim.x - 1 - (int)blockIdx.x;  // heavy first
    const int h    = blockIdx.y;
    const int b    = blockIdx.z;
    const int q0   = qt2 * 128;
    const int wloc = (warp >> 2) * 64 + (warp & 3) * 16;
    const int wbase = q0 + wloc;
    const int nt   = 2 * qt2 + 2;

    const size_t base  = (size_t)b * SS * EE + (size_t)h * DD;
    const size_t vbase = ((size_t)b * HH + h) * DD * SS;

    const int srow = tid >> 2;           // 0..63
    const int scol = (tid & 3) * 16;     // halves
    const uint32_t k_d0 = (uint32_t)__cvta_generic_to_shared(&Ks0[srow * KPH + scol]);
    const uint32_t k_d1 = (uint32_t)__cvta_generic_to_shared(&Ks1[srow * KPH + scol]);
    const uint32_t v_d0 = (uint32_t)__cvta_generic_to_shared(&Vt0[srow * KPH + scol]);
    const uint32_t v_d1 = (uint32_t)__cvta_generic_to_shared(&Vt1[srow * KPH + scol]);

    // ---- stage Q (fp16, pre-scaled) into Ks region [128][KPH] ----
    {
        const int qrow = tid >> 1;
        const int qh   = (tid & 1) * 32;
        const __half* qsrc = &Qg[base + (size_t)(q0 + qrow) * EE + qh];
        uint32_t qd = (uint32_t)__cvta_generic_to_shared(&fsm[qrow * KPH + qh]);
        #pragma unroll
        for (int c = 0; c < 4; c++)
            cp16(qd + c * 16, qsrc + c * 8);
        cp_commit();
    }
    cp_wait<0>();
    __syncthreads();

    uint32_t qf[4][4];
    #pragma unroll
    for (int ks = 0; ks < 4; ks++) {
        int r = wloc + gid;
        qf[ks][0] = *(const uint32_t*)&fsm[(r    ) * KPH + ks * 16 + 2 * tig];
        qf[ks][1] = *(const uint32_t*)&fsm[(r + 8) * KPH + ks * 16 + 2 * tig];
        qf[ks][2] = *(const uint32_t*)&fsm[(r    ) * KPH + ks * 16 + 8 + 2 * tig];
        qf[ks][3] = *(const uint32_t*)&fsm[(r + 8) * KPH + ks * 16 + 8 + 2 * tig];
    }
    __syncthreads();   // all warps done reading Q before tile0 overwrites

    // prefetch K/V tile 0 into buffer 0
    {
        const __half* kg = &Kg [base  + (size_t)srow * EE + scol];
        const __half* vg = &Vtg[vbase + (size_t)srow * SS + scol];
        cp16(k_d0,      kg);     cp16(k_d0 + 16, kg + 8);
        cp16(v_d0,      vg);     cp16(v_d0 + 16, vg + 8);
        cp_commit();
    }

    float oacc[8][4] = {};
    float m0r = -CUDART_INF_F, m1r = -CUDART_INF_F;
    float l0 = 0.f, l1 = 0.f;
    const int r0g = wbase + gid;
    const int r1g = r0g + 8;

    for (int kt = 0; kt < nt; kt++) {
        const int k0 = kt * 64;
        const int buf = kt & 1;

        if (kt + 1 < nt) {
            const int kn = (kt + 1) * 64;
            const __half* kg = &Kg [base  + (size_t)(kn + srow) * EE + scol];
            const __half* vg = &Vtg[vbase + (size_t)srow * SS + kn + scol];
            const uint32_t kd = buf ? k_d0 : k_d1;
            const uint32_t vd = buf ? v_d0 : v_d1;
            cp16(kd,      kg);     cp16(kd + 16, kg + 8);
            cp16(vd,      vg);     cp16(vd + 16, vg + 8);
            cp_commit();
            cp_wait<1>();
        } else {
            cp_wait<0>();
        }
        __syncthreads();

        // fully-masked tile for this warp: identity update, skip compute
        if (k0 <= wbase + 15) {
            const __half* Ks_ = buf ? Ks1 : Ks0;
            const __half* Vt_ = buf ? Vt1 : Vt0;

            // S = Q @ K^T
            float sacc[8][4] = {};
            #pragma unroll
            for (int t = 0; t < 8; t++) {
                #pragma unroll
                for (int ks = 0; ks < 4; ks++) {
                    uint32_t b0 = *(const uint32_t*)&Ks_[(t * 8 + gid) * KPH + ks * 16 + 2 * tig];
                    uint32_t b1 = *(const uint32_t*)&Ks_[(t * 8 + gid) * KPH + ks * 16 + 8 + 2 * tig];
                    mma16(sacc[t], qf[ks], b0, b1);
                }
            }

            // causal mask (tiles crossing this warp's diagonal)
            if (k0 + 63 > wbase) {
                #pragma unroll
                for (int t = 0; t < 8; t++) {
                    int c = k0 + t * 8 + 2 * tig;
                    if (c     > r0g) sacc[t][0] = -CUDART_INF_F;
                    if (c + 1 > r0g) sacc[t][1] = -CUDART_INF_F;
                    if (c     > r1g) sacc[t][2] = -CUDART_INF_F;
                    if (c + 1 > r1g) sacc[t][3] = -CUDART_INF_F;
                }
            }

            // online softmax
            float vm0 = -CUDART_INF_F, vm1 = -CUDART_INF_F;
            #pragma unroll
            for (int t = 0; t < 8; t++) {
                vm0 = fmaxf(vm0, fmaxf(sacc[t][0], sacc[t][1]));
                vm1 = fmaxf(vm1, fmaxf(sacc[t][2], sacc[t][3]));
            }
            vm0 = fmaxf(vm0, __shfl_xor_sync(0xffffffffu, vm0, 1));
            vm0 = fmaxf(vm0, __shfl_xor_sync(0xffffffffu, vm0, 2));
            vm1 = fmaxf(vm1, __shfl_xor_sync(0xffffffffu, vm1, 1));
            vm1 = fmaxf(vm1, __shfl_xor_sync(0xffffffffu, vm1, 2));

            float mn0 = fmaxf(m0r, vm0), mn1 = fmaxf(m1r, vm1);
            float al0 = __expf(m0r - mn0), al1 = __expf(m1r - mn1);

            float sum0 = 0.f, sum1 = 0.f;
            #pragma unroll
            for (int t = 0; t < 8; t++) {
                float p0 = __expf(sacc[t][0] - mn0);
                float p1 = __expf(sacc[t][1] - mn0);
                float p2 = __expf(sacc[t][2] - mn1);
                float p3 = __expf(sacc[t][3] - mn1);
                sacc[t][0] = p0; sacc[t][1] = p1; sacc[t][2] = p2; sacc[t][3] = p3;
                sum0 += p0 + p1;
                sum1 += p2 + p3;
            }
            sum0 += __shfl_xor_sync(0xffffffffu, sum0, 1);
            sum0 += __shfl_xor_sync(0xffffffffu, sum0, 2);
            sum1 += __shfl_xor_sync(0xffffffffu, sum1, 1);
            sum1 += __shfl_xor_sync(0xffffffffu, sum1, 2);

            l0 = l0 * al0 + sum0;  m0r = mn0;
            l1 = l1 * al1 + sum1;  m1r = mn1;
            #pragma unroll
            for (int dt = 0; dt < 8; dt++) {
                oacc[dt][0] *= al0; oacc[dt][1] *= al0;
                oacc[dt][2] *= al1; oacc[dt][3] *= al1;
            }

            // P C-frags -> PV A-frags (pure register repack)
            uint32_t pf[4][4];
            #pragma unroll
            for (int ks = 0; ks < 4; ks++) {
                pf[ks][0] = packh2(sacc[2 * ks    ][0], sacc[2 * ks    ][1]);
                pf[ks][1] = packh2(sacc[2 * ks    ][2], sacc[2 * ks    ][3]);
                pf[ks][2] = packh2(sacc[2 * ks + 1][0], sacc[2 * ks + 1][1]);
                pf[ks][3] = packh2(sacc[2 * ks + 1][2], sacc[2 * ks + 1][3]);
            }

            // O += P @ V
            #pragma unroll
            for (int ks = 0; ks < 4; ks++) {
                #pragma unroll
                for (int dt = 0; dt < 8; dt++) {
                    uint32_t b0 = *(const uint32_t*)&Vt_[(dt * 8 + gid) * KPH + ks * 16 + 2 * tig];
                    uint32_t b1 = *(const uint32_t*)&Vt_[(dt * 8 + gid) * KPH + ks * 16 + 8 + 2 * tig];
                    mma16(oacc[dt], pf[ks], b0, b1);
                }
            }
        }

        __syncthreads();
    }

    // normalize + store ctx (fp16)
    float inv0 = 1.f / l0, inv1 = 1.f / l1;
    #pragma unroll
    for (int dt = 0; dt < 8; dt++) {
        int c = dt * 8 + 2 * tig;
        *(__half2*)&ctx[base + (size_t)r0g * EE + c] =
            __floats2half2_rn(oacc[dt][0] * inv0, oacc[dt][1] * inv0);
        *(__half2*)&ctx[base + (size_t)r1g * EE + c] =
            __floats2half2_rn(oacc[dt][2] * inv1, oacc[dt][3] * inv1);
    }
}

// ---------------------------------------------------------------------------
// Launch
// ---------------------------------------------------------------------------
extern "C" void kernel_launch(void* const* d_in, const int* in_sizes, int n_in,
                              void* d_out, int out_size)
{
    (void)in_sizes; (void)n_in; (void)out_size;
    const float* x  = (const float*)d_in[0];
    const float* Wq = (const float*)d_in[1];
    const float* bq = (const float*)d_in[2];
    const float* Wk = (const float*)d_in[3];
    const float* bk = (const float*)d_in[4];
    const float* Wv = (const float*)d_in[5];
    const float* bv = (const float*)d_in[6];
    const float* Wo = (const float*)d_in[7];
    const float* bo = (const float*)d_in[8];
    float* out = (float*)d_out;

    __half *qp, *kp, *vp, *vtp, *cp, *xt, *wq, *wk, *wv, *wo;
    cudaGetSymbolAddress((void**)&qp,  g_q);
    cudaGetSymbolAddress((void**)&kp,  g_k);
    cudaGetSymbolAddress((void**)&vp,  g_v);
    cudaGetSymbolAddress((void**)&vtp, g_vt);
    cudaGetSymbolAddress((void**)&cp,  g_ctx);
    cudaGetSymbolAddress((void**)&xt,  g_xt);
    cudaGetSymbolAddress((void**)&wq,  g_wq);
    cudaGetSymbolAddress((void**)&wk,  g_wk);
    cudaGetSymbolAddress((void**)&wv,  g_wv);
    cudaGetSymbolAddress((void**)&wo,  g_wo);

    // prologue conversions
    const int xn4 = BB * SS * EE / 4;
    cvt_h<<<xn4 / 256, 256>>>(x, xt, xn4);
    dim3 tb(32, 8);
    transcvt_w4<<<dim3(EE / 32, EE / 32, 4), tb>>>(Wq, Wk, Wv, Wo, wq, wk, wv, wo);

    cudaFuncSetAttribute(gemm16_qkv, cudaFuncAttributeMaxDynamicSharedMemorySize, HSMEM);
    cudaFuncSetAttribute(gemm16_out, cudaFuncAttributeMaxDynamicSharedMemorySize, HSMEM);
    cudaFuncSetAttribute(flash16, cudaFuncAttributeMaxDynamicSharedMemorySize, FSMEM);

    dim3 gqkv(EE / 128, (BB * SS) / 128, 3);
    gemm16_qkv<<<gqkv, 128, HSMEM>>>(xt, wq, bq, wk, bk, wv, bv, qp, kp, vp);

    trans_v<<<dim3(SS / 32, 2 * HH, BB), tb>>>(vp, vtp);

    flash16<<<dim3(SS / 128, HH, BB), 256, FSMEM>>>(qp, kp, vtp, cp);

    dim3 go(EE / 128, (BB * SS) / 128);
    gemm16_out<<<go, 128, HSMEM>>>(cp, wo, bo, out);
}

// round 10
// speedup vs baseline: 2.5733x; 1.0681x over previous
#include <cuda_runtime.h>
#include <cuda_fp16.h>
#include <math_constants.h>
#include <cstdint>

// Problem constants
#define BB 2
#define SS 2048
#define EE 1024
#define HH 16
#define DD 64

// Scratch (device globals — allocation-free rule)
__device__ __half g_q [BB * SS * EE];
__device__ __half g_k [BB * SS * EE];
__device__ __half g_v [BB * SS * EE];
__device__ __half g_vt[BB * HH * DD * SS];   // V transposed: [b][h][d][s]
__device__ __half g_ctx[BB * SS * EE];
__device__ __half g_xt[BB * SS * EE];        // x in fp16
__device__ __half g_wq[EE * EE];             // W^T in fp16: [N][K]
__device__ __half g_wk[EE * EE];
__device__ __half g_wv[EE * EE];
__device__ __half g_wo[EE * EE];

// ---------------------------------------------------------------------------
// helpers
// ---------------------------------------------------------------------------
__device__ __forceinline__ void mma16(
    float* c, const uint32_t* a, uint32_t b0, uint32_t b1)
{
    asm volatile(
        "mma.sync.aligned.m16n8k16.row.col.f32.f16.f16.f32 "
        "{%0,%1,%2,%3},{%4,%5,%6,%7},{%8,%9},{%0,%1,%2,%3};\n"
        : "+f"(c[0]), "+f"(c[1]), "+f"(c[2]), "+f"(c[3])
        : "r"(a[0]), "r"(a[1]), "r"(a[2]), "r"(a[3]), "r"(b0), "r"(b1));
}

__device__ __forceinline__ void ldsm4(
    uint32_t& r0, uint32_t& r1, uint32_t& r2, uint32_t& r3, uint32_t addr)
{
    asm volatile(
        "ldmatrix.sync.aligned.m8n8.x4.shared.b16 {%0,%1,%2,%3}, [%4];"
        : "=r"(r0), "=r"(r1), "=r"(r2), "=r"(r3) : "r"(addr));
}

__device__ __forceinline__ uint32_t packh2(float a, float b) {
    __half2 h = __floats2half2_rn(a, b);
    return *(uint32_t*)&h;
}

__device__ __forceinline__ void cp16(uint32_t smem_dst, const void* gsrc) {
    asm volatile("cp.async.cg.shared.global [%0], [%1], 16;\n"
                 :: "r"(smem_dst), "l"(gsrc));
}
__device__ __forceinline__ void cp_commit() {
    asm volatile("cp.async.commit_group;\n");
}
template<int N>
__device__ __forceinline__ void cp_wait() {
    asm volatile("cp.async.wait_group %0;\n" :: "n"(N));
}

// ---------------------------------------------------------------------------
// prologue conversions
// ---------------------------------------------------------------------------
__global__ __launch_bounds__(256) void cvt_h(
    const float* __restrict__ src, __half* __restrict__ dst, int n4)
{
    int i = blockIdx.x * blockDim.x + threadIdx.x;
    if (i < n4) {
        float4 v = ((const float4*)src)[i];
        __half2 h0 = __floats2half2_rn(v.x, v.y);
        __half2 h1 = __floats2half2_rn(v.z, v.w);
        *(uint2*)&dst[4 * i] = make_uint2(*(uint32_t*)&h0, *(uint32_t*)&h1);
    }
}

// fp32 W[K][N] -> fp16 W^T[N][K], 4 weights in one launch
__global__ __launch_bounds__(256) void transcvt_w4(
    const float* __restrict__ W0, const float* __restrict__ W1,
    const float* __restrict__ W2, const float* __restrict__ W3,
    __half* __restrict__ T0, __half* __restrict__ T1,
    __half* __restrict__ T2, __half* __restrict__ T3)
{
    const int z = blockIdx.z;
    const float* W = (z == 0) ? W0 : (z == 1) ? W1 : (z == 2) ? W2 : W3;
    __half* Wt     = (z == 0) ? T0 : (z == 1) ? T1 : (z == 2) ? T2 : T3;

    __shared__ float t[32][33];
    const int n0 = blockIdx.x * 32;
    const int k0 = blockIdx.y * 32;
    const int tx = threadIdx.x;
    const int ty = threadIdx.y;
    #pragma unroll
    for (int i = 0; i < 32; i += 8)
        t[ty + i][tx] = W[(size_t)(k0 + ty + i) * EE + n0 + tx];
    __syncthreads();
    #pragma unroll
    for (int i = 0; i < 32; i += 8)
        Wt[(size_t)(n0 + ty + i) * EE + k0 + tx] = __float2half(t[tx][ty + i]);
}

// v[b][s][h*64+d] (fp16) -> vt[b][h][d][s] (fp16)
__global__ __launch_bounds__(256) void trans_v(
    const __half* __restrict__ v, __half* __restrict__ vt)
{
    __shared__ __half t[32][33];
    const int s0 = blockIdx.x * 32;
    const int h  = blockIdx.y >> 1;
    const int d0 = (blockIdx.y & 1) * 32;
    const int b  = blockIdx.z;
    const int tx = threadIdx.x;
    const int ty = threadIdx.y;
    #pragma unroll
    for (int i = 0; i < 32; i += 8)
        t[ty + i][tx] = v[((size_t)b * SS + s0 + ty + i) * EE + h * DD + d0 + tx];
    __syncthreads();
    #pragma unroll
    for (int i = 0; i < 32; i += 8)
        vt[(((size_t)b * HH + h) * DD + d0 + ty + i) * SS + s0 + tx] = t[tx][ty + i];
}

// ---------------------------------------------------------------------------
// fp16 GEMM: C[4096,1024] = A @ W + bias, W as W^T fp16.
// CTA 128x128, 128 threads (4 warps 2x2), warp tile 64x64, BK=32,
// 3-stage cp.async, fragments via ldmatrix.x4.
// mode: 0 = fp32 out, 1 = fp16 out, 2 = fp16 out * 0.125
// ---------------------------------------------------------------------------
#define HBK 32
#define HAP 40
#define HSTG (128 * HAP)
#define HSMEM (3 * 2 * HSTG * 2)   // 61440 bytes

__device__ __forceinline__ void gemm16_body(
    const __half* __restrict__ A, const __half* __restrict__ Wt,
    const float* __restrict__ bias, void* Cv, int mode)
{
    extern __shared__ __half hsm[];
    __half* As = hsm;
    __half* Bs = hsm + 3 * HSTG;

    const int tid  = threadIdx.x;
    const int lane = tid & 31;
    const int warp = tid >> 5;
    const int gid  = lane >> 2;
    const int tig  = lane & 3;
    const int wm   = warp >> 1;
    const int wn   = warp & 1;
    const int m0   = blockIdx.y * 128;
    const int n0   = blockIdx.x * 128;

    const uint32_t a_base = (uint32_t)__cvta_generic_to_shared(As);
    const uint32_t b_base = (uint32_t)__cvta_generic_to_shared(Bs);

    // ldmatrix per-thread fragment offsets (element units)
    // A: matrices (r0,c0),(r8,c0),(r0,c8),(r8,c8) -> regs a0,a1,a2,a3
    const int arow_f = wm * 64 + (lane & 7) + ((lane >> 3) & 1) * 8;
    const int acol_f = ((lane >> 4) & 1) * 8;
    // B: matrices (r0,c0),(r0,c8),(r8,c0),(r8,c8) -> b0(j),b1(j),b0(j+1),b1(j+1)
    const int brow_f = wn * 64 + (lane & 7) + ((lane >> 4) & 1) * 8;
    const int bcol_f = ((lane >> 3) & 1) * 8;

    float acc[4][8][4] = {};
    const int nt = EE / HBK;

    #pragma unroll
    for (int s = 0; s < 2; s++) {
        const __half* ag = &A [(size_t)(m0 + tid) * EE + s * HBK];
        const __half* bg = &Wt[(size_t)(n0 + tid) * EE + s * HBK];
        uint32_t ad = a_base + (s * HSTG + tid * HAP) * 2;
        uint32_t bd = b_base + (s * HSTG + tid * HAP) * 2;
        #pragma unroll
        for (int c = 0; c < 4; c++) {
            cp16(ad + c * 16, ag + c * 8);
            cp16(bd + c * 16, bg + c * 8);
        }
        cp_commit();
    }

    for (int kt = 0; kt < nt; kt++) {
        cp_wait<1>();
        __syncthreads();

        if (kt + 2 < nt) {
            const int s = (kt + 2) % 3;
            const __half* ag = &A [(size_t)(m0 + tid) * EE + (kt + 2) * HBK];
            const __half* bg = &Wt[(size_t)(n0 + tid) * EE + (kt + 2) * HBK];
            uint32_t ad = a_base + (s * HSTG + tid * HAP) * 2;
            uint32_t bd = b_base + (s * HSTG + tid * HAP) * 2;
            #pragma unroll
            for (int c = 0; c < 4; c++) {
                cp16(ad + c * 16, ag + c * 8);
                cp16(bd + c * 16, bg + c * 8);
            }
        }
        cp_commit();

        const uint32_t as_s = a_base + (kt % 3) * HSTG * 2;
        const uint32_t bs_s = b_base + (kt % 3) * HSTG * 2;

        #pragma unroll
        for (int ks = 0; ks < 2; ks++) {
            uint32_t af[4][4];
            #pragma unroll
            for (int i = 0; i < 4; i++)
                ldsm4(af[i][0], af[i][1], af[i][2], af[i][3],
                      as_s + (uint32_t)((arow_f + i * 16) * HAP + ks * 16 + acol_f) * 2);
            #pragma unroll
            for (int jp = 0; jp < 4; jp++) {
                uint32_t b00, b01, b10, b11;
                ldsm4(b00, b01, b10, b11,
                      bs_s + (uint32_t)((brow_f + jp * 16) * HAP + ks * 16 + bcol_f) * 2);
                #pragma unroll
                for (int i = 0; i < 4; i++) {
                    mma16(acc[i][2 * jp    ], af[i], b00, b01);
                    mma16(acc[i][2 * jp + 1], af[i], b10, b11);
                }
            }
        }
    }

    #pragma unroll
    for (int i = 0; i < 4; i++) {
        int r = m0 + wm * 64 + i * 16 + gid;
        #pragma unroll
        for (int j = 0; j < 8; j++) {
            int c = n0 + wn * 64 + j * 8 + 2 * tig;
            float2 bb = *(const float2*)&bias[c];
            float v00 = acc[i][j][0] + bb.x;
            float v01 = acc[i][j][1] + bb.y;
            float v10 = acc[i][j][2] + bb.x;
            float v11 = acc[i][j][3] + bb.y;
            if (mode == 0) {
                float* C = (float*)Cv;
                *(float2*)&C[(size_t)r * EE + c]       = make_float2(v00, v01);
                *(float2*)&C[(size_t)(r + 8) * EE + c] = make_float2(v10, v11);
            } else {
                if (mode == 2) { v00 *= 0.125f; v01 *= 0.125f; v10 *= 0.125f; v11 *= 0.125f; }
                __half* C = (__half*)Cv;
                *(__half2*)&C[(size_t)r * EE + c]       = __floats2half2_rn(v00, v01);
                *(__half2*)&C[(size_t)(r + 8) * EE + c] = __floats2half2_rn(v10, v11);
            }
        }
    }
}

__global__ __launch_bounds__(128) void gemm16_qkv(
    const __half* __restrict__ x,
    const __half* __restrict__ Wq, const float* __restrict__ bq,
    const __half* __restrict__ Wk, const float* __restrict__ bk,
    const __half* __restrict__ Wv, const float* __restrict__ bv,
    __half* __restrict__ qp, __half* __restrict__ kp, __half* __restrict__ vp)
{
    const int z = blockIdx.z;
    const __half* W  = (z == 0) ? Wq : (z == 1) ? Wk : Wv;
    const float* bb  = (z == 0) ? bq : (z == 1) ? bk : bv;
    __half* C        = (z == 0) ? qp : (z == 1) ? kp : vp;
    gemm16_body(x, W, bb, C, (z == 0) ? 2 : 1);
}

__global__ __launch_bounds__(128) void gemm16_out(
    const __half* __restrict__ A, const __half* __restrict__ Wt,
    const float* __restrict__ bias, float* __restrict__ C)
{
    gemm16_body(A, Wt, bias, C, 0);
}

// ---------------------------------------------------------------------------
// fp16 flash attention, causal. 256 threads = 8 warps.
// P in registers (C->A frag identity); all smem fragments via ldmatrix.
// smem: Ks0,Ks1,Vt0,Vt1 [64][72] = 36864 B. Q staged via Ks region.
// ---------------------------------------------------------------------------
#define KPH 72
#define FSMEM (4 * 64 * KPH * 2)   // 36864 bytes

__global__ __launch_bounds__(256, 2) void flash16(
    const __half* __restrict__ Qg, const __half* __restrict__ Kg,
    const __half* __restrict__ Vtg, __half* __restrict__ ctx)
{
    extern __shared__ __half fsm[];

    const int tid  = threadIdx.x;
    const int lane = tid & 31;
    const int warp = tid >> 5;
    const int gid  = lane >> 2;
    const int tig  = lane & 3;
    const int qt2  = (int)gridDim.x - 1 - (int)blockIdx.x;  // heavy first
    const int h    = blockIdx.y;
    const int b    = blockIdx.z;
    const int q0   = qt2 * 128;
    const int wloc = (warp >> 2) * 64 + (warp & 3) * 16;
    const int wbase = q0 + wloc;
    const int nt   = 2 * qt2 + 2;

    const size_t base  = (size_t)b * SS * EE + (size_t)h * DD;
    const size_t vbase = ((size_t)b * HH + h) * DD * SS;

    const uint32_t smem0 = (uint32_t)__cvta_generic_to_shared(fsm);
    const uint32_t KS0 = smem0;
    const uint32_t KS1 = smem0 + 64 * KPH * 2;
    const uint32_t VT0 = smem0 + 2 * 64 * KPH * 2;
    const uint32_t VT1 = smem0 + 3 * 64 * KPH * 2;

    const int srow = tid >> 2;
    const int scol = (tid & 3) * 16;
    const uint32_t soff = (uint32_t)(srow * KPH + scol) * 2;

    // ldmatrix offsets
    // A-type (Q): (r0,c0),(r8,c0),(r0,c8),(r8,c8)
    const int qrow_f = wloc + (lane & 7) + ((lane >> 3) & 1) * 8;
    const int qcol_f = ((lane >> 4) & 1) * 8;
    // B-type (K rows / Vt rows): (r0,c0),(r0,c8),(r8,c0),(r8,c8)
    const int krow_f = (lane & 7) + ((lane >> 4) & 1) * 8;
    const int kcol_f = ((lane >> 3) & 1) * 8;

    // ---- stage Q (fp16, pre-scaled) into Ks region [128][KPH] ----
    {
        const int qrow = tid >> 1;
        const int qh   = (tid & 1) * 32;
        const __half* qsrc = &Qg[base + (size_t)(q0 + qrow) * EE + qh];
        uint32_t qd = smem0 + (uint32_t)(qrow * KPH + qh) * 2;
        #pragma unroll
        for (int c = 0; c < 4; c++)
            cp16(qd + c * 16, qsrc + c * 8);
        cp_commit();
    }
    cp_wait<0>();
    __syncthreads();

    uint32_t qf[4][4];
    #pragma unroll
    for (int ks = 0; ks < 4; ks++)
        ldsm4(qf[ks][0], qf[ks][1], qf[ks][2], qf[ks][3],
              smem0 + (uint32_t)(qrow_f * KPH + ks * 16 + qcol_f) * 2);
    __syncthreads();   // all warps done reading Q before tile0 overwrites

    // prefetch K/V tile 0 into buffer 0
    {
        const __half* kg = &Kg [base  + (size_t)srow * EE + scol];
        const __half* vg = &Vtg[vbase + (size_t)srow * SS + scol];
        cp16(KS0 + soff,      kg);   cp16(KS0 + soff + 16, kg + 8);
        cp16(VT0 + soff,      vg);   cp16(VT0 + soff + 16, vg + 8);
        cp_commit();
    }

    float oacc[8][4] = {};
    float m0r = -CUDART_INF_F, m1r = -CUDART_INF_F;
    float l0 = 0.f, l1 = 0.f;
    const int r0g = wbase + gid;
    const int r1g = r0g + 8;

    for (int kt = 0; kt < nt; kt++) {
        const int k0 = kt * 64;
        const int buf = kt & 1;

        if (kt + 1 < nt) {
            const int kn = (kt + 1) * 64;
            const __half* kg = &Kg [base  + (size_t)(kn + srow) * EE + scol];
            const __half* vg = &Vtg[vbase + (size_t)srow * SS + kn + scol];
            const uint32_t kd = (buf ? KS0 : KS1) + soff;
            const uint32_t vd = (buf ? VT0 : VT1) + soff;
            cp16(kd,      kg);   cp16(kd + 16, kg + 8);
            cp16(vd,      vg);   cp16(vd + 16, vg + 8);
            cp_commit();
            cp_wait<1>();
        } else {
            cp_wait<0>();
        }
        __syncthreads();

        if (k0 <= wbase + 15) {   // not fully masked for this warp
            const uint32_t KS_ = buf ? KS1 : KS0;
            const uint32_t VT_ = buf ? VT1 : VT0;

            // S = Q @ K^T  (ldmatrix loads two t-tiles per x4)
            float sacc[8][4] = {};
            #pragma unroll
            for (int tp = 0; tp < 4; tp++) {
                #pragma unroll
                for (int ks = 0; ks < 4; ks++) {
                    uint32_t b00, b01, b10, b11;
                    ldsm4(b00, b01, b10, b11,
                          KS_ + (uint32_t)((krow_f + tp * 16) * KPH + ks * 16 + kcol_f) * 2);
                    mma16(sacc[2 * tp    ], qf[ks], b00, b01);
                    mma16(sacc[2 * tp + 1], qf[ks], b10, b11);
                }
            }

            // causal mask
            if (k0 + 63 > wbase) {
                #pragma unroll
                for (int t = 0; t < 8; t++) {
                    int c = k0 + t * 8 + 2 * tig;
                    if (c     > r0g) sacc[t][0] = -CUDART_INF_F;
                    if (c + 1 > r0g) sacc[t][1] = -CUDART_INF_F;
                    if (c     > r1g) sacc[t][2] = -CUDART_INF_F;
                    if (c + 1 > r1g) sacc[t][3] = -CUDART_INF_F;
                }
            }

            // online softmax
            float vm0 = -CUDART_INF_F, vm1 = -CUDART_INF_F;
            #pragma unroll
            for (int t = 0; t < 8; t++) {
                vm0 = fmaxf(vm0, fmaxf(sacc[t][0], sacc[t][1]));
                vm1 = fmaxf(vm1, fmaxf(sacc[t][2], sacc[t][3]));
            }
            vm0 = fmaxf(vm0, __shfl_xor_sync(0xffffffffu, vm0, 1));
            vm0 = fmaxf(vm0, __shfl_xor_sync(0xffffffffu, vm0, 2));
            vm1 = fmaxf(vm1, __shfl_xor_sync(0xffffffffu, vm1, 1));
            vm1 = fmaxf(vm1, __shfl_xor_sync(0xffffffffu, vm1, 2));

            float mn0 = fmaxf(m0r, vm0), mn1 = fmaxf(m1r, vm1);
            float al0 = __expf(m0r - mn0), al1 = __expf(m1r - mn1);

            float sum0 = 0.f, sum1 = 0.f;
            #pragma unroll
            for (int t = 0; t < 8; t++) {
                float p0 = __expf(sacc[t][0] - mn0);
                float p1 = __expf(sacc[t][1] - mn0);
                float p2 = __expf(sacc[t][2] - mn1);
                float p3 = __expf(sacc[t][3] - mn1);
                sacc[t][0] = p0; sacc[t][1] = p1; sacc[t][2] = p2; sacc[t][3] = p3;
                sum0 += p0 + p1;
                sum1 += p2 + p3;
            }
            sum0 += __shfl_xor_sync(0xffffffffu, sum0, 1);
            sum0 += __shfl_xor_sync(0xffffffffu, sum0, 2);
            sum1 += __shfl_xor_sync(0xffffffffu, sum1, 1);
            sum1 += __shfl_xor_sync(0xffffffffu, sum1, 2);

            l0 = l0 * al0 + sum0;  m0r = mn0;
            l1 = l1 * al1 + sum1;  m1r = mn1;
            #pragma unroll
            for (int dt = 0; dt < 8; dt++) {
                oacc[dt][0] *= al0; oacc[dt][1] *= al0;
                oacc[dt][2] *= al1; oacc[dt][3] *= al1;
            }

            // P C-frags -> PV A-frags (register repack)
            uint32_t pf[4][4];
            #pragma unroll
            for (int ks = 0; ks < 4; ks++) {
                pf[ks][0] = packh2(sacc[2 * ks    ][0], sacc[2 * ks    ][1]);
                pf[ks][1] = packh2(sacc[2 * ks    ][2], sacc[2 * ks    ][3]);
                pf[ks][2] = packh2(sacc[2 * ks + 1][0], sacc[2 * ks + 1][1]);
                pf[ks][3] = packh2(sacc[2 * ks + 1][2], sacc[2 * ks + 1][3]);
            }

            // O += P @ V (ldmatrix loads two dt-tiles per x4)
            #pragma unroll
            for (int dp = 0; dp < 4; dp++) {
                #pragma unroll
                for (int ks = 0; ks < 4; ks++) {
                    uint32_t b00, b01, b10, b11;
                    ldsm4(b00, b01, b10, b11,
                          VT_ + (uint32_t)((krow_f + dp * 16) * KPH + ks * 16 + kcol_f) * 2);
                    mma16(oacc[2 * dp    ], pf[ks], b00, b01);
                    mma16(oacc[2 * dp + 1], pf[ks], b10, b11);
                }
            }
        }

        __syncthreads();
    }

    // normalize + store ctx (fp16)
    float inv0 = 1.f / l0, inv1 = 1.f / l1;
    #pragma unroll
    for (int dt = 0; dt < 8; dt++) {
        int c = dt * 8 + 2 * tig;
        *(__half2*)&ctx[base + (size_t)r0g * EE + c] =
            __floats2half2_rn(oacc[dt][0] * inv0, oacc[dt][1] * inv0);
        *(__half2*)&ctx[base + (size_t)r1g * EE + c] =
            __floats2half2_rn(oacc[dt][2] * inv1, oacc[dt][3] * inv1);
    }
}

// ---------------------------------------------------------------------------
// Launch
// ---------------------------------------------------------------------------
extern "C" void kernel_launch(void* const* d_in, const int* in_sizes, int n_in,
                              void* d_out, int out_size)
{
    (void)in_sizes; (void)n_in; (void)out_size;
    const float* x  = (const float*)d_in[0];
    const float* Wq = (const float*)d_in[1];
    const float* bq = (const float*)d_in[2];
    const float* Wk = (const float*)d_in[3];
    const float* bk = (const float*)d_in[4];
    const float* Wv = (const float*)d_in[5];
    const float* bv = (const float*)d_in[6];
    const float* Wo = (const float*)d_in[7];
    const float* bo = (const float*)d_in[8];
    float* out = (float*)d_out;

    __half *qp, *kp, *vp, *vtp, *cp, *xt, *wq, *wk, *wv, *wo;
    cudaGetSymbolAddress((void**)&qp,  g_q);
    cudaGetSymbolAddress((void**)&kp,  g_k);
    cudaGetSymbolAddress((void**)&vp,  g_v);
    cudaGetSymbolAddress((void**)&vtp, g_vt);
    cudaGetSymbolAddress((void**)&cp,  g_ctx);
    cudaGetSymbolAddress((void**)&xt,  g_xt);
    cudaGetSymbolAddress((void**)&wq,  g_wq);
    cudaGetSymbolAddress((void**)&wk,  g_wk);
    cudaGetSymbolAddress((void**)&wv,  g_wv);
    cudaGetSymbolAddress((void**)&wo,  g_wo);

    const int xn4 = BB * SS * EE / 4;
    cvt_h<<<xn4 / 256, 256>>>(x, xt, xn4);
    dim3 tb(32, 8);
    transcvt_w4<<<dim3(EE / 32, EE / 32, 4), tb>>>(Wq, Wk, Wv, Wo, wq, wk, wv, wo);

    cudaFuncSetAttribute(gemm16_qkv, cudaFuncAttributeMaxDynamicSharedMemorySize, HSMEM);
    cudaFuncSetAttribute(gemm16_out, cudaFuncAttributeMaxDynamicSharedMemorySize, HSMEM);
    cudaFuncSetAttribute(flash16, cudaFuncAttributeMaxDynamicSharedMemorySize, FSMEM);

    dim3 gqkv(EE / 128, (BB * SS) / 128, 3);
    gemm16_qkv<<<gqkv, 128, HSMEM>>>(xt, wq, bq, wk, bk, wv, bv, qp, kp, vp);

    trans_v<<<dim3(SS / 32, 2 * HH, BB), tb>>>(vp, vtp);

    flash16<<<dim3(SS / 128, HH, BB), 256, FSMEM>>>(qp, kp, vtp, cp);

    dim3 go(EE / 128, (BB * SS) / 128);
    gemm16_out<<<go, 128, HSMEM>>>(cp, wo, bo, out);
}

// round 11
// speedup vs baseline: 2.6042x; 1.0120x over previous
#include <cuda_runtime.h>
#include <cuda_fp16.h>
#include <math_constants.h>
#include <cstdint>

// Problem constants
#define BB 2
#define SS 2048
#define EE 1024
#define HH 16
#define DD 64

// Scratch (device globals — allocation-free rule)
__device__ __half g_q [BB * SS * EE];
__device__ __half g_k [BB * SS * EE];
__device__ __half g_v [BB * SS * EE];
__device__ __half g_vt[BB * HH * DD * SS];   // V transposed: [b][h][d][s]
__device__ __half g_ctx[BB * SS * EE];
__device__ __half g_xt[BB * SS * EE];        // x in fp16
__device__ __half g_wq[EE * EE];             // W^T in fp16: [N][K]
__device__ __half g_wk[EE * EE];
__device__ __half g_wv[EE * EE];
__device__ __half g_wo[EE * EE];

// Q pre-scale: (1/sqrt(64)) * log2(e)  -> scores in log2 units
#define QSCALE 0.1803368801111204f

// ---------------------------------------------------------------------------
// helpers
// ---------------------------------------------------------------------------
__device__ __forceinline__ void mma16(
    float* c, const uint32_t* a, uint32_t b0, uint32_t b1)
{
    asm volatile(
        "mma.sync.aligned.m16n8k16.row.col.f32.f16.f16.f32 "
        "{%0,%1,%2,%3},{%4,%5,%6,%7},{%8,%9},{%0,%1,%2,%3};\n"
        : "+f"(c[0]), "+f"(c[1]), "+f"(c[2]), "+f"(c[3])
        : "r"(a[0]), "r"(a[1]), "r"(a[2]), "r"(a[3]), "r"(b0), "r"(b1));
}

__device__ __forceinline__ void ldsm4(
    uint32_t& r0, uint32_t& r1, uint32_t& r2, uint32_t& r3, uint32_t addr)
{
    asm volatile(
        "ldmatrix.sync.aligned.m8n8.x4.shared.b16 {%0,%1,%2,%3}, [%4];"
        : "=r"(r0), "=r"(r1), "=r"(r2), "=r"(r3) : "r"(addr));
}

__device__ __forceinline__ float ex2f(float x) {
    float r;
    asm("ex2.approx.f32 %0, %1;" : "=f"(r) : "f"(x));
    return r;
}

// pack two fp32 (log2-domain) args to half2 and exp2 them in one MUFU op
__device__ __forceinline__ uint32_t ex2_h2(float a, float b) {
    __half2 h = __floats2half2_rn(a, b);
    uint32_t r;
    asm("ex2.approx.f16x2 %0, %1;" : "=r"(r) : "r"(*(uint32_t*)&h));
    return r;
}

__device__ __forceinline__ void cp16(uint32_t smem_dst, const void* gsrc) {
    asm volatile("cp.async.cg.shared.global [%0], [%1], 16;\n"
                 :: "r"(smem_dst), "l"(gsrc));
}
__device__ __forceinline__ void cp_commit() {
    asm volatile("cp.async.commit_group;\n");
}
template<int N>
__device__ __forceinline__ void cp_wait() {
    asm volatile("cp.async.wait_group %0;\n" :: "n"(N));
}

// ---------------------------------------------------------------------------
// prologue conversions
// ---------------------------------------------------------------------------
__global__ __launch_bounds__(256) void cvt_h(
    const float* __restrict__ src, __half* __restrict__ dst, int n4)
{
    int i = blockIdx.x * blockDim.x + threadIdx.x;
    if (i < n4) {
        float4 v = ((const float4*)src)[i];
        __half2 h0 = __floats2half2_rn(v.x, v.y);
        __half2 h1 = __floats2half2_rn(v.z, v.w);
        *(uint2*)&dst[4 * i] = make_uint2(*(uint32_t*)&h0, *(uint32_t*)&h1);
    }
}

// fp32 W[K][N] -> fp16 W^T[N][K], 4 weights in one launch
__global__ __launch_bounds__(256) void transcvt_w4(
    const float* __restrict__ W0, const float* __restrict__ W1,
    const float* __restrict__ W2, const float* __restrict__ W3,
    __half* __restrict__ T0, __half* __restrict__ T1,
    __half* __restrict__ T2, __half* __restrict__ T3)
{
    const int z = blockIdx.z;
    const float* W = (z == 0) ? W0 : (z == 1) ? W1 : (z == 2) ? W2 : W3;
    __half* Wt     = (z == 0) ? T0 : (z == 1) ? T1 : (z == 2) ? T2 : T3;

    __shared__ float t[32][33];
    const int n0 = blockIdx.x * 32;
    const int k0 = blockIdx.y * 32;
    const int tx = threadIdx.x;
    const int ty = threadIdx.y;
    #pragma unroll
    for (int i = 0; i < 32; i += 8)
        t[ty + i][tx] = W[(size_t)(k0 + ty + i) * EE + n0 + tx];
    __syncthreads();
    #pragma unroll
    for (int i = 0; i < 32; i += 8)
        Wt[(size_t)(n0 + ty + i) * EE + k0 + tx] = __float2half(t[tx][ty + i]);
}

// v[b][s][h*64+d] (fp16) -> vt[b][h][d][s] (fp16)
__global__ __launch_bounds__(256) void trans_v(
    const __half* __restrict__ v, __half* __restrict__ vt)
{
    __shared__ __half t[32][33];
    const int s0 = blockIdx.x * 32;
    const int h  = blockIdx.y >> 1;
    const int d0 = (blockIdx.y & 1) * 32;
    const int b  = blockIdx.z;
    const int tx = threadIdx.x;
    const int ty = threadIdx.y;
    #pragma unroll
    for (int i = 0; i < 32; i += 8)
        t[ty + i][tx] = v[((size_t)b * SS + s0 + ty + i) * EE + h * DD + d0 + tx];
    __syncthreads();
    #pragma unroll
    for (int i = 0; i < 32; i += 8)
        vt[(((size_t)b * HH + h) * DD + d0 + ty + i) * SS + s0 + tx] = t[tx][ty + i];
}

// ---------------------------------------------------------------------------
// fp16 GEMM: C[4096,1024] = A @ W + bias, W as W^T fp16.
// CTA 128x128, 128 threads (4 warps 2x2), warp tile 64x64, BK=32,
// 3-stage cp.async, fragments via ldmatrix.x4.
// mode: 0 = fp32 out, 1 = fp16 out, 2 = fp16 out * QSCALE
// ---------------------------------------------------------------------------
#define HBK 32
#define HAP 40
#define HSTG (128 * HAP)
#define HSMEM (3 * 2 * HSTG * 2)   // 61440 bytes

__device__ __forceinline__ void gemm16_body(
    const __half* __restrict__ A, const __half* __restrict__ Wt,
    const float* __restrict__ bias, void* Cv, int mode)
{
    extern __shared__ __half hsm[];
    __half* As = hsm;
    __half* Bs = hsm + 3 * HSTG;

    const int tid  = threadIdx.x;
    const int lane = tid & 31;
    const int warp = tid >> 5;
    const int gid  = lane >> 2;
    const int tig  = lane & 3;
    const int wm   = warp >> 1;
    const int wn   = warp & 1;
    const int m0   = blockIdx.y * 128;
    const int n0   = blockIdx.x * 128;

    const uint32_t a_base = (uint32_t)__cvta_generic_to_shared(As);
    const uint32_t b_base = (uint32_t)__cvta_generic_to_shared(Bs);

    const int arow_f = wm * 64 + (lane & 7) + ((lane >> 3) & 1) * 8;
    const int acol_f = ((lane >> 4) & 1) * 8;
    const int brow_f = wn * 64 + (lane & 7) + ((lane >> 4) & 1) * 8;
    const int bcol_f = ((lane >> 3) & 1) * 8;

    float acc[4][8][4] = {};
    const int nt = EE / HBK;

    #pragma unroll
    for (int s = 0; s < 2; s++) {
        const __half* ag = &A [(size_t)(m0 + tid) * EE + s * HBK];
        const __half* bg = &Wt[(size_t)(n0 + tid) * EE + s * HBK];
        uint32_t ad = a_base + (s * HSTG + tid * HAP) * 2;
        uint32_t bd = b_base + (s * HSTG + tid * HAP) * 2;
        #pragma unroll
        for (int c = 0; c < 4; c++) {
            cp16(ad + c * 16, ag + c * 8);
            cp16(bd + c * 16, bg + c * 8);
        }
        cp_commit();
    }

    for (int kt = 0; kt < nt; kt++) {
        cp_wait<1>();
        __syncthreads();

        if (kt + 2 < nt) {
            const int s = (kt + 2) % 3;
            const __half* ag = &A [(size_t)(m0 + tid) * EE + (kt + 2) * HBK];
            const __half* bg = &Wt[(size_t)(n0 + tid) * EE + (kt + 2) * HBK];
            uint32_t ad = a_base + (s * HSTG + tid * HAP) * 2;
            uint32_t bd = b_base + (s * HSTG + tid * HAP) * 2;
            #pragma unroll
            for (int c = 0; c < 4; c++) {
                cp16(ad + c * 16, ag + c * 8);
                cp16(bd + c * 16, bg + c * 8);
            }
        }
        cp_commit();

        const uint32_t as_s = a_base + (kt % 3) * HSTG * 2;
        const uint32_t bs_s = b_base + (kt % 3) * HSTG * 2;

        #pragma unroll
        for (int ks = 0; ks < 2; ks++) {
            uint32_t af[4][4];
            #pragma unroll
            for (int i = 0; i < 4; i++)
                ldsm4(af[i][0], af[i][1], af[i][2], af[i][3],
                      as_s + (uint32_t)((arow_f + i * 16) * HAP + ks * 16 + acol_f) * 2);
            #pragma unroll
            for (int jp = 0; jp < 4; jp++) {
                uint32_t b00, b01, b10, b11;
                ldsm4(b00, b01, b10, b11,
                      bs_s + (uint32_t)((brow_f + jp * 16) * HAP + ks * 16 + bcol_f) * 2);
                #pragma unroll
                for (int i = 0; i < 4; i++) {
                    mma16(acc[i][2 * jp    ], af[i], b00, b01);
                    mma16(acc[i][2 * jp + 1], af[i], b10, b11);
                }
            }
        }
    }

    #pragma unroll
    for (int i = 0; i < 4; i++) {
        int r = m0 + wm * 64 + i * 16 + gid;
        #pragma unroll
        for (int j = 0; j < 8; j++) {
            int c = n0 + wn * 64 + j * 8 + 2 * tig;
            float2 bb = *(const float2*)&bias[c];
            float v00 = acc[i][j][0] + bb.x;
            float v01 = acc[i][j][1] + bb.y;
            float v10 = acc[i][j][2] + bb.x;
            float v11 = acc[i][j][3] + bb.y;
            if (mode == 0) {
                float* C = (float*)Cv;
                *(float2*)&C[(size_t)r * EE + c]       = make_float2(v00, v01);
                *(float2*)&C[(size_t)(r + 8) * EE + c] = make_float2(v10, v11);
            } else {
                if (mode == 2) {
                    v00 *= QSCALE; v01 *= QSCALE; v10 *= QSCALE; v11 *= QSCALE;
                }
                __half* C = (__half*)Cv;
                *(__half2*)&C[(size_t)r * EE + c]       = __floats2half2_rn(v00, v01);
                *(__half2*)&C[(size_t)(r + 8) * EE + c] = __floats2half2_rn(v10, v11);
            }
        }
    }
}

__global__ __launch_bounds__(128) void gemm16_qkv(
    const __half* __restrict__ x,
    const __half* __restrict__ Wq, const float* __restrict__ bq,
    const __half* __restrict__ Wk, const float* __restrict__ bk,
    const __half* __restrict__ Wv, const float* __restrict__ bv,
    __half* __restrict__ qp, __half* __restrict__ kp, __half* __restrict__ vp)
{
    const int z = blockIdx.z;
    const __half* W  = (z == 0) ? Wq : (z == 1) ? Wk : Wv;
    const float* bb  = (z == 0) ? bq : (z == 1) ? bk : bv;
    __half* C        = (z == 0) ? qp : (z == 1) ? kp : vp;
    gemm16_body(x, W, bb, C, (z == 0) ? 2 : 1);
}

__global__ __launch_bounds__(128) void gemm16_out(
    const __half* __restrict__ A, const __half* __restrict__ Wt,
    const float* __restrict__ bias, float* __restrict__ C)
{
    gemm16_body(A, Wt, bias, C, 0);
}

// ---------------------------------------------------------------------------
// fp16 flash attention, causal (scores in log2 domain). 256 threads = 8 warps.
// P computed directly in fp16 via ex2.approx.f16x2 (halves MUFU traffic and
// IS the PV A-fragment). Row sums accumulate fp32 from the same quantized P.
// ---------------------------------------------------------------------------
#define KPH 72
#define FSMEM (4 * 64 * KPH * 2)   // 36864 bytes

__global__ __launch_bounds__(256, 2) void flash16(
    const __half* __restrict__ Qg, const __half* __restrict__ Kg,
    const __half* __restrict__ Vtg, __half* __restrict__ ctx)
{
    extern __shared__ __half fsm[];

    const int tid  = threadIdx.x;
    const int lane = tid & 31;
    const int warp = tid >> 5;
    const int gid  = lane >> 2;
    const int tig  = lane & 3;
    const int qt2  = (int)gridDim.x - 1 - (int)blockIdx.x;  // heavy first
    const int h    = blockIdx.y;
    const int b    = blockIdx.z;
    const int q0   = qt2 * 128;
    const int wloc = (warp >> 2) * 64 + (warp & 3) * 16;
    const int wbase = q0 + wloc;
    const int nt   = 2 * qt2 + 2;

    const size_t base  = (size_t)b * SS * EE + (size_t)h * DD;
    const size_t vbase = ((size_t)b * HH + h) * DD * SS;

    const uint32_t smem0 = (uint32_t)__cvta_generic_to_shared(fsm);
    const uint32_t KS0 = smem0;
    const uint32_t KS1 = smem0 + 64 * KPH * 2;
    const uint32_t VT0 = smem0 + 2 * 64 * KPH * 2;
    const uint32_t VT1 = smem0 + 3 * 64 * KPH * 2;

    const int srow = tid >> 2;
    const int scol = (tid & 3) * 16;
    const uint32_t soff = (uint32_t)(srow * KPH + scol) * 2;

    const int qrow_f = wloc + (lane & 7) + ((lane >> 3) & 1) * 8;
    const int qcol_f = ((lane >> 4) & 1) * 8;
    const int krow_f = (lane & 7) + ((lane >> 4) & 1) * 8;
    const int kcol_f = ((lane >> 3) & 1) * 8;

    // ---- stage Q (fp16, pre-scaled by QSCALE) into Ks region ----
    {
        const int qrow = tid >> 1;
        const int qh   = (tid & 1) * 32;
        const __half* qsrc = &Qg[base + (size_t)(q0 + qrow) * EE + qh];
        uint32_t qd = smem0 + (uint32_t)(qrow * KPH + qh) * 2;
        #pragma unroll
        for (int c = 0; c < 4; c++)
            cp16(qd + c * 16, qsrc + c * 8);
        cp_commit();
    }
    cp_wait<0>();
    __syncthreads();

    uint32_t qf[4][4];
    #pragma unroll
    for (int ks = 0; ks < 4; ks++)
        ldsm4(qf[ks][0], qf[ks][1], qf[ks][2], qf[ks][3],
              smem0 + (uint32_t)(qrow_f * KPH + ks * 16 + qcol_f) * 2);
    __syncthreads();

    // prefetch K/V tile 0 into buffer 0
    {
        const __half* kg = &Kg [base  + (size_t)srow * EE + scol];
        const __half* vg = &Vtg[vbase + (size_t)srow * SS + scol];
        cp16(KS0 + soff,      kg);   cp16(KS0 + soff + 16, kg + 8);
        cp16(VT0 + soff,      vg);   cp16(VT0 + soff + 16, vg + 8);
        cp_commit();
    }

    float oacc[8][4] = {};
    float m0r = -CUDART_INF_F, m1r = -CUDART_INF_F;
    float l0 = 0.f, l1 = 0.f;
    const int r0g = wbase + gid;
    const int r1g = r0g + 8;

    for (int kt = 0; kt < nt; kt++) {
        const int k0 = kt * 64;
        const int buf = kt & 1;

        if (kt + 1 < nt) {
            const int kn = (kt + 1) * 64;
            const __half* kg = &Kg [base  + (size_t)(kn + srow) * EE + scol];
            const __half* vg = &Vtg[vbase + (size_t)srow * SS + kn + scol];
            const uint32_t kd = (buf ? KS0 : KS1) + soff;
            const uint32_t vd = (buf ? VT0 : VT1) + soff;
            cp16(kd,      kg);   cp16(kd + 16, kg + 8);
            cp16(vd,      vg);   cp16(vd + 16, vg + 8);
            cp_commit();
            cp_wait<1>();
        } else {
            cp_wait<0>();
        }
        __syncthreads();

        if (k0 <= wbase + 15) {   // not fully masked for this warp
            const uint32_t KS_ = buf ? KS1 : KS0;
            const uint32_t VT_ = buf ? VT1 : VT0;

            // S = Q @ K^T  (log2-domain scores)
            float sacc[8][4] = {};
            #pragma unroll
            for (int tp = 0; tp < 4; tp++) {
                #pragma unroll
                for (int ks = 0; ks < 4; ks++) {
                    uint32_t b00, b01, b10, b11;
                    ldsm4(b00, b01, b10, b11,
                          KS_ + (uint32_t)((krow_f + tp * 16) * KPH + ks * 16 + kcol_f) * 2);
                    mma16(sacc[2 * tp    ], qf[ks], b00, b01);
                    mma16(sacc[2 * tp + 1], qf[ks], b10, b11);
                }
            }

            // causal mask
            if (k0 + 63 > wbase) {
                #pragma unroll
                for (int t = 0; t < 8; t++) {
                    int c = k0 + t * 8 + 2 * tig;
                    if (c     > r0g) sacc[t][0] = -CUDART_INF_F;
                    if (c + 1 > r0g) sacc[t][1] = -CUDART_INF_F;
                    if (c     > r1g) sacc[t][2] = -CUDART_INF_F;
                    if (c + 1 > r1g) sacc[t][3] = -CUDART_INF_F;
                }
            }

            // online softmax (log2 domain)
            float vm0 = -CUDART_INF_F, vm1 = -CUDART_INF_F;
            #pragma unroll
            for (int t = 0; t < 8; t++) {
                vm0 = fmaxf(vm0, fmaxf(sacc[t][0], sacc[t][1]));
                vm1 = fmaxf(vm1, fmaxf(sacc[t][2], sacc[t][3]));
            }
            vm0 = fmaxf(vm0, __shfl_xor_sync(0xffffffffu, vm0, 1));
            vm0 = fmaxf(vm0, __shfl_xor_sync(0xffffffffu, vm0, 2));
            vm1 = fmaxf(vm1, __shfl_xor_sync(0xffffffffu, vm1, 1));
            vm1 = fmaxf(vm1, __shfl_xor_sync(0xffffffffu, vm1, 2));

            float mn0 = fmaxf(m0r, vm0), mn1 = fmaxf(m1r, vm1);
            float al0 = ex2f(m0r - mn0), al1 = ex2f(m1r - mn1);

            // P = 2^(s - mn) computed in fp16x2 — result IS the PV A-fragment
            uint32_t pf[4][4];
            float sum0 = 0.f, sum1 = 0.f;
            #pragma unroll
            for (int ks = 0; ks < 4; ks++) {
                #pragma unroll
                for (int u = 0; u < 2; u++) {
                    const float* s = sacc[2 * ks + u];
                    uint32_t e01 = ex2_h2(s[0] - mn0, s[1] - mn0);
                    uint32_t e23 = ex2_h2(s[2] - mn1, s[3] - mn1);
                    pf[ks][2 * u    ] = e01;
                    pf[ks][2 * u + 1] = e23;
                    float2 f01 = __half22float2(*(__half2*)&e01);
                    float2 f23 = __half22float2(*(__half2*)&e23);
                    sum0 += f01.x + f01.y;
                    sum1 += f23.x + f23.y;
                }
            }
            sum0 += __shfl_xor_sync(0xffffffffu, sum0, 1);
            sum0 += __shfl_xor_sync(0xffffffffu, sum0, 2);
            sum1 += __shfl_xor_sync(0xffffffffu, sum1, 1);
            sum1 += __shfl_xor_sync(0xffffffffu, sum1, 2);

            l0 = l0 * al0 + sum0;  m0r = mn0;
            l1 = l1 * al1 + sum1;  m1r = mn1;
            #pragma unroll
            for (int dt = 0; dt < 8; dt++) {
                oacc[dt][0] *= al0; oacc[dt][1] *= al0;
                oacc[dt][2] *= al1; oacc[dt][3] *= al1;
            }

            // O += P @ V
            #pragma unroll
            for (int dp = 0; dp < 4; dp++) {
                #pragma unroll
                for (int ks = 0; ks < 4; ks++) {
                    uint32_t b00, b01, b10, b11;
                    ldsm4(b00, b01, b10, b11,
                          VT_ + (uint32_t)((krow_f + dp * 16) * KPH + ks * 16 + kcol_f) * 2);
                    mma16(oacc[2 * dp    ], pf[ks], b00, b01);
                    mma16(oacc[2 * dp + 1], pf[ks], b10, b11);
                }
            }
        }

        __syncthreads();
    }

    // normalize + store ctx (fp16)
    float inv0 = 1.f / l0, inv1 = 1.f / l1;
    #pragma unroll
    for (int dt = 0; dt < 8; dt++) {
        int c = dt * 8 + 2 * tig;
        *(__half2*)&ctx[base + (size_t)r0g * EE + c] =
            __floats2half2_rn(oacc[dt][0] * inv0, oacc[dt][1] * inv0);
        *(__half2*)&ctx[base + (size_t)r1g * EE + c] =
            __floats2half2_rn(oacc[dt][2] * inv1, oacc[dt][3] * inv1);
    }
}

// ---------------------------------------------------------------------------
// Launch
// ---------------------------------------------------------------------------
extern "C" void kernel_launch(void* const* d_in, const int* in_sizes, int n_in,
                              void* d_out, int out_size)
{
    (void)in_sizes; (void)n_in; (void)out_size;
    const float* x  = (const float*)d_in[0];
    const float* Wq = (const float*)d_in[1];
    const float* bq = (const float*)d_in[2];
    const float* Wk = (const float*)d_in[3];
    const float* bk = (const float*)d_in[4];
    const float* Wv = (const float*)d_in[5];
    const float* bv = (const float*)d_in[6];
    const float* Wo = (const float*)d_in[7];
    const float* bo = (const float*)d_in[8];
    float* out = (float*)d_out;

    __half *qp, *kp, *vp, *vtp, *cp, *xt, *wq, *wk, *wv, *wo;
    cudaGetSymbolAddress((void**)&qp,  g_q);
    cudaGetSymbolAddress((void**)&kp,  g_k);
    cudaGetSymbolAddress((void**)&vp,  g_v);
    cudaGetSymbolAddress((void**)&vtp, g_vt);
    cudaGetSymbolAddress((void**)&cp,  g_ctx);
    cudaGetSymbolAddress((void**)&xt,  g_xt);
    cudaGetSymbolAddress((void**)&wq,  g_wq);
    cudaGetSymbolAddress((void**)&wk,  g_wk);
    cudaGetSymbolAddress((void**)&wv,  g_wv);
    cudaGetSymbolAddress((void**)&wo,  g_wo);

    const int xn4 = BB * SS * EE / 4;
    cvt_h<<<xn4 / 256, 256>>>(x, xt, xn4);
    dim3 tb(32, 8);
    transcvt_w4<<<dim3(EE / 32, EE / 32, 4), tb>>>(Wq, Wk, Wv, Wo, wq, wk, wv, wo);

    cudaFuncSetAttribute(gemm16_qkv, cudaFuncAttributeMaxDynamicSharedMemorySize, HSMEM);
    cudaFuncSetAttribute(gemm16_out, cudaFuncAttributeMaxDynamicSharedMemorySize, HSMEM);
    cudaFuncSetAttribute(flash16, cudaFuncAttributeMaxDynamicSharedMemorySize, FSMEM);

    dim3 gqkv(EE / 128, (BB * SS) / 128, 3);
    gemm16_qkv<<<gqkv, 128, HSMEM>>>(xt, wq, bq, wk, bk, wv, bv, qp, kp, vp);

    trans_v<<<dim3(SS / 32, 2 * HH, BB), tb>>>(vp, vtp);

    flash16<<<dim3(SS / 128, HH, BB), 256, FSMEM>>>(qp, kp, vtp, cp);

    dim3 go(EE / 128, (BB * SS) / 128);
    gemm16_out<<<go, 128, HSMEM>>>(cp, wo, bo, out);
}

// round 12
// speedup vs baseline: 2.6382x; 1.0130x over previous
#include <cuda_runtime.h>
#include <cuda_fp16.h>
#include <math_constants.h>
#include <cstdint>

// Problem constants
#define BB 2
#define SS 2048
#define EE 1024
#define HH 16
#define DD 64

// Scratch (device globals — allocation-free rule)
__device__ __half g_q [BB * SS * EE];
__device__ __half g_k [BB * SS * EE];
__device__ __half g_v [BB * SS * EE];
__device__ __half g_ctx[BB * SS * EE];
__device__ __half g_xt[BB * SS * EE];        // x in fp16
__device__ __half g_wq[EE * EE];             // W^T in fp16: [N][K]
__device__ __half g_wk[EE * EE];
__device__ __half g_wv[EE * EE];
__device__ __half g_wo[EE * EE];

// Q pre-scale: (1/sqrt(64)) * log2(e)  -> scores in log2 units
#define QSCALE 0.1803368801111204f

// ---------------------------------------------------------------------------
// helpers
// ---------------------------------------------------------------------------
__device__ __forceinline__ void mma16(
    float* c, const uint32_t* a, uint32_t b0, uint32_t b1)
{
    asm volatile(
        "mma.sync.aligned.m16n8k16.row.col.f32.f16.f16.f32 "
        "{%0,%1,%2,%3},{%4,%5,%6,%7},{%8,%9},{%0,%1,%2,%3};\n"
        : "+f"(c[0]), "+f"(c[1]), "+f"(c[2]), "+f"(c[3])
        : "r"(a[0]), "r"(a[1]), "r"(a[2]), "r"(a[3]), "r"(b0), "r"(b1));
}

__device__ __forceinline__ void ldsm4(
    uint32_t& r0, uint32_t& r1, uint32_t& r2, uint32_t& r3, uint32_t addr)
{
    asm volatile(
        "ldmatrix.sync.aligned.m8n8.x4.shared.b16 {%0,%1,%2,%3}, [%4];"
        : "=r"(r0), "=r"(r1), "=r"(r2), "=r"(r3) : "r"(addr));
}

__device__ __forceinline__ void ldsm4t(
    uint32_t& r0, uint32_t& r1, uint32_t& r2, uint32_t& r3, uint32_t addr)
{
    asm volatile(
        "ldmatrix.sync.aligned.m8n8.x4.trans.shared.b16 {%0,%1,%2,%3}, [%4];"
        : "=r"(r0), "=r"(r1), "=r"(r2), "=r"(r3) : "r"(addr));
}

__device__ __forceinline__ float ex2f(float x) {
    float r;
    asm("ex2.approx.f32 %0, %1;" : "=f"(r) : "f"(x));
    return r;
}

// pack two fp32 (log2-domain) args to half2 and exp2 them in one MUFU op
__device__ __forceinline__ uint32_t ex2_h2(float a, float b) {
    __half2 h = __floats2half2_rn(a, b);
    uint32_t r;
    asm("ex2.approx.f16x2 %0, %1;" : "=r"(r) : "r"(*(uint32_t*)&h));
    return r;
}

__device__ __forceinline__ void cp16(uint32_t smem_dst, const void* gsrc) {
    asm volatile("cp.async.cg.shared.global [%0], [%1], 16;\n"
                 :: "r"(smem_dst), "l"(gsrc));
}
__device__ __forceinline__ void cp_commit() {
    asm volatile("cp.async.commit_group;\n");
}
template<int N>
__device__ __forceinline__ void cp_wait() {
    asm volatile("cp.async.wait_group %0;\n" :: "n"(N));
}

// ---------------------------------------------------------------------------
// prologue conversions
// ---------------------------------------------------------------------------
__global__ __launch_bounds__(256) void cvt_h(
    const float* __restrict__ src, __half* __restrict__ dst, int n4)
{
    int i = blockIdx.x * blockDim.x + threadIdx.x;
    if (i < n4) {
        float4 v = ((const float4*)src)[i];
        __half2 h0 = __floats2half2_rn(v.x, v.y);
        __half2 h1 = __floats2half2_rn(v.z, v.w);
        *(uint2*)&dst[4 * i] = make_uint2(*(uint32_t*)&h0, *(uint32_t*)&h1);
    }
}

// fp32 W[K][N] -> fp16 W^T[N][K], 4 weights in one launch
__global__ __launch_bounds__(256) void transcvt_w4(
    const float* __restrict__ W0, const float* __restrict__ W1,
    const float* __restrict__ W2, const float* __restrict__ W3,
    __half* __restrict__ T0, __half* __restrict__ T1,
    __half* __restrict__ T2, __half* __restrict__ T3)
{
    const int z = blockIdx.z;
    const float* W = (z == 0) ? W0 : (z == 1) ? W1 : (z == 2) ? W2 : W3;
    __half* Wt     = (z == 0) ? T0 : (z == 1) ? T1 : (z == 2) ? T2 : T3;

    __shared__ float t[32][33];
    const int n0 = blockIdx.x * 32;
    const int k0 = blockIdx.y * 32;
    const int tx = threadIdx.x;
    const int ty = threadIdx.y;
    #pragma unroll
    for (int i = 0; i < 32; i += 8)
        t[ty + i][tx] = W[(size_t)(k0 + ty + i) * EE + n0 + tx];
    __syncthreads();
    #pragma unroll
    for (int i = 0; i < 32; i += 8)
        Wt[(size_t)(n0 + ty + i) * EE + k0 + tx] = __float2half(t[tx][ty + i]);
}

// ---------------------------------------------------------------------------
// fp16 GEMM: C[4096,1024] = A @ W + bias, W as W^T fp16. (unchanged R10/R11)
// ---------------------------------------------------------------------------
#define HBK 32
#define HAP 40
#define HSTG (128 * HAP)
#define HSMEM (3 * 2 * HSTG * 2)   // 61440 bytes

__device__ __forceinline__ void gemm16_body(
    const __half* __restrict__ A, const __half* __restrict__ Wt,
    const float* __restrict__ bias, void* Cv, int mode)
{
    extern __shared__ __half hsm[];
    __half* As = hsm;
    __half* Bs = hsm + 3 * HSTG;

    const int tid  = threadIdx.x;
    const int lane = tid & 31;
    const int warp = tid >> 5;
    const int gid  = lane >> 2;
    const int tig  = lane & 3;
    const int wm   = warp >> 1;
    const int wn   = warp & 1;
    const int m0   = blockIdx.y * 128;
    const int n0   = blockIdx.x * 128;

    const uint32_t a_base = (uint32_t)__cvta_generic_to_shared(As);
    const uint32_t b_base = (uint32_t)__cvta_generic_to_shared(Bs);

    const int arow_f = wm * 64 + (lane & 7) + ((lane >> 3) & 1) * 8;
    const int acol_f = ((lane >> 4) & 1) * 8;
    const int brow_f = wn * 64 + (lane & 7) + ((lane >> 4) & 1) * 8;
    const int bcol_f = ((lane >> 3) & 1) * 8;

    float acc[4][8][4] = {};
    const int nt = EE / HBK;

    #pragma unroll
    for (int s = 0; s < 2; s++) {
        const __half* ag = &A [(size_t)(m0 + tid) * EE + s * HBK];
        const __half* bg = &Wt[(size_t)(n0 + tid) * EE + s * HBK];
        uint32_t ad = a_base + (s * HSTG + tid * HAP) * 2;
        uint32_t bd = b_base + (s * HSTG + tid * HAP) * 2;
        #pragma unroll
        for (int c = 0; c < 4; c++) {
            cp16(ad + c * 16, ag + c * 8);
            cp16(bd + c * 16, bg + c * 8);
        }
        cp_commit();
    }

    for (int kt = 0; kt < nt; kt++) {
        cp_wait<1>();
        __syncthreads();

        if (kt + 2 < nt) {
            const int s = (kt + 2) % 3;
            const __half* ag = &A [(size_t)(m0 + tid) * EE + (kt + 2) * HBK];
            const __half* bg = &Wt[(size_t)(n0 + tid) * EE + (kt + 2) * HBK];
            uint32_t ad = a_base + (s * HSTG + tid * HAP) * 2;
            uint32_t bd = b_base + (s * HSTG + tid * HAP) * 2;
            #pragma unroll
            for (int c = 0; c < 4; c++) {
                cp16(ad + c * 16, ag + c * 8);
                cp16(bd + c * 16, bg + c * 8);
            }
        }
        cp_commit();

        const uint32_t as_s = a_base + (kt % 3) * HSTG * 2;
        const uint32_t bs_s = b_base + (kt % 3) * HSTG * 2;

        #pragma unroll
        for (int ks = 0; ks < 2; ks++) {
            uint32_t af[4][4];
            #pragma unroll
            for (int i = 0; i < 4; i++)
                ldsm4(af[i][0], af[i][1], af[i][2], af[i][3],
                      as_s + (uint32_t)((arow_f + i * 16) * HAP + ks * 16 + acol_f) * 2);
            #pragma unroll
            for (int jp = 0; jp < 4; jp++) {
                uint32_t b00, b01, b10, b11;
                ldsm4(b00, b01, b10, b11,
                      bs_s + (uint32_t)((brow_f + jp * 16) * HAP + ks * 16 + bcol_f) * 2);
                #pragma unroll
                for (int i = 0; i < 4; i++) {
                    mma16(acc[i][2 * jp    ], af[i], b00, b01);
                    mma16(acc[i][2 * jp + 1], af[i], b10, b11);
                }
            }
        }
    }

    #pragma unroll
    for (int i = 0; i < 4; i++) {
        int r = m0 + wm * 64 + i * 16 + gid;
        #pragma unroll
        for (int j = 0; j < 8; j++) {
            int c = n0 + wn * 64 + j * 8 + 2 * tig;
            float2 bb = *(const float2*)&bias[c];
            float v00 = acc[i][j][0] + bb.x;
            float v01 = acc[i][j][1] + bb.y;
            float v10 = acc[i][j][2] + bb.x;
            float v11 = acc[i][j][3] + bb.y;
            if (mode == 0) {
                float* C = (float*)Cv;
                *(float2*)&C[(size_t)r * EE + c]       = make_float2(v00, v01);
                *(float2*)&C[(size_t)(r + 8) * EE + c] = make_float2(v10, v11);
            } else {
                if (mode == 2) {
                    v00 *= QSCALE; v01 *= QSCALE; v10 *= QSCALE; v11 *= QSCALE;
                }
                __half* C = (__half*)Cv;
                *(__half2*)&C[(size_t)r * EE + c]       = __floats2half2_rn(v00, v01);
                *(__half2*)&C[(size_t)(r + 8) * EE + c] = __floats2half2_rn(v10, v11);
            }
        }
    }
}

__global__ __launch_bounds__(128) void gemm16_qkv(
    const __half* __restrict__ x,
    const __half* __restrict__ Wq, const float* __restrict__ bq,
    const __half* __restrict__ Wk, const float* __restrict__ bk,
    const __half* __restrict__ Wv, const float* __restrict__ bv,
    __half* __restrict__ qp, __half* __restrict__ kp, __half* __restrict__ vp)
{
    const int z = blockIdx.z;
    const __half* W  = (z == 0) ? Wq : (z == 1) ? Wk : Wv;
    const float* bb  = (z == 0) ? bq : (z == 1) ? bk : bv;
    __half* C        = (z == 0) ? qp : (z == 1) ? kp : vp;
    gemm16_body(x, W, bb, C, (z == 0) ? 2 : 1);
}

__global__ __launch_bounds__(128) void gemm16_out(
    const __half* __restrict__ A, const __half* __restrict__ Wt,
    const float* __restrict__ bias, float* __restrict__ C)
{
    gemm16_body(A, Wt, bias, C, 0);
}

// ---------------------------------------------------------------------------
// fp16 flash attention, causal (log2-domain scores). 256 threads = 8 warps.
// V read in NATURAL [key][d] layout; PV B-fragments via ldmatrix.trans
// (no pre-transpose kernel). 3-stage cp.async K/V pipeline (2-tile lead).
// smem: 3 stages x (K 64x72 + V 64x72) halves = 55296 B.
// ---------------------------------------------------------------------------
#define KPH 72
#define STAGE_H (2 * 64 * KPH)            // halves per stage (K then V)
#define FSMEM (3 * STAGE_H * 2)           // 55296 bytes

__global__ __launch_bounds__(256, 2) void flash16(
    const __half* __restrict__ Qg, const __half* __restrict__ Kg,
    const __half* __restrict__ Vg, __half* __restrict__ ctx)
{
    extern __shared__ __half fsm[];

    const int tid  = threadIdx.x;
    const int lane = tid & 31;
    const int warp = tid >> 5;
    const int gid  = lane >> 2;
    const int tig  = lane & 3;
    const int qt2  = (int)gridDim.x - 1 - (int)blockIdx.x;  // heavy first
    const int h    = blockIdx.y;
    const int b    = blockIdx.z;
    const int q0   = qt2 * 128;
    const int wloc = (warp >> 2) * 64 + (warp & 3) * 16;
    const int wbase = q0 + wloc;
    const int nt   = 2 * qt2 + 2;

    const size_t base = (size_t)b * SS * EE + (size_t)h * DD;

    const uint32_t smem0 = (uint32_t)__cvta_generic_to_shared(fsm);

    // staging: 64 rows x 64 halves per tile; thread covers 32 halves
    const int srow = tid >> 2;
    const int scol = (tid & 3) * 16;
    const uint32_t soff = (uint32_t)(srow * KPH + scol) * 2;

    // fragment lane offsets
    // A-type (Q): matrices (r0,c0),(r8,c0),(r0,c8),(r8,c8)
    const int qrow_f = wloc + (lane & 7) + ((lane >> 3) & 1) * 8;
    const int qcol_f = ((lane >> 4) & 1) * 8;
    // B-type non-trans (K tile [key][d]): (key0,d0),(key0,d8),(key8,d0),(key8,d8)
    const int krow_f = (lane & 7) + ((lane >> 4) & 1) * 8;
    const int kcol_f = ((lane >> 3) & 1) * 8;
    // B-type TRANS (V tile [key][d]): groups (key0,d0),(key8,d0),(key0,d8),(key8,d8)
    const int vrow_t = (lane & 7) + ((lane >> 3) & 1) * 8;
    const int vcol_t = ((lane >> 4) & 1) * 8;

    // ---- stage Q (fp16, pre-scaled by QSCALE) into stage-0 region ----
    {
        const int qrow = tid >> 1;
        const int qh   = (tid & 1) * 32;
        const __half* qsrc = &Qg[base + (size_t)(q0 + qrow) * EE + qh];
        uint32_t qd = smem0 + (uint32_t)(qrow * KPH + qh) * 2;
        #pragma unroll
        for (int c = 0; c < 4; c++)
            cp16(qd + c * 16, qsrc + c * 8);
        cp_commit();
    }
    cp_wait<0>();
    __syncthreads();

    uint32_t qf[4][4];
    #pragma unroll
    for (int ks = 0; ks < 4; ks++)
        ldsm4(qf[ks][0], qf[ks][1], qf[ks][2], qf[ks][3],
              smem0 + (uint32_t)(qrow_f * KPH + ks * 16 + qcol_f) * 2);
    __syncthreads();   // all warps done reading Q before tile0 overwrites

    // prefetch tiles 0 and 1 (each its own commit group)
    #pragma unroll
    for (int pt = 0; pt < 2; pt++) {
        if (pt < nt) {
            const uint32_t st = smem0 + (uint32_t)(pt * STAGE_H) * 2;
            const __half* kg = &Kg[base + (size_t)(pt * 64 + srow) * EE + scol];
            const __half* vg = &Vg[base + (size_t)(pt * 64 + srow) * EE + scol];
            cp16(st + soff,      kg);   cp16(st + soff + 16, kg + 8);
            cp16(st + (uint32_t)(64 * KPH) * 2 + soff,      vg);
            cp16(st + (uint32_t)(64 * KPH) * 2 + soff + 16, vg + 8);
        }
        cp_commit();
    }

    float oacc[8][4] = {};
    float m0r = -CUDART_INF_F, m1r = -CUDART_INF_F;
    float l0 = 0.f, l1 = 0.f;
    const int r0g = wbase + gid;
    const int r1g = r0g + 8;

    for (int kt = 0; kt < nt; kt++) {
        const int k0 = kt * 64;

        __syncthreads();   // all warps done with tile kt-1 -> its buffer reusable

        if (kt + 2 < nt) {
            const int kn = (kt + 2) * 64;
            const uint32_t st = smem0 + (uint32_t)(((kt + 2) % 3) * STAGE_H) * 2;
            const __half* kg = &Kg[base + (size_t)(kn + srow) * EE + scol];
            const __half* vg = &Vg[base + (size_t)(kn + srow) * EE + scol];
            cp16(st + soff,      kg);   cp16(st + soff + 16, kg + 8);
            cp16(st + (uint32_t)(64 * KPH) * 2 + soff,      vg);
            cp16(st + (uint32_t)(64 * KPH) * 2 + soff + 16, vg + 8);
        }
        cp_commit();       // uniform group accounting
        cp_wait<2>();      // tile kt has landed (issued 2 iterations ago)
        __syncthreads();   // make tile kt visible to all warps

        if (k0 <= wbase + 15) {   // not fully masked for this warp
            const uint32_t KS_ = smem0 + (uint32_t)((kt % 3) * STAGE_H) * 2;
            const uint32_t VS_ = KS_ + (uint32_t)(64 * KPH) * 2;

            // S = Q @ K^T
            float sacc[8][4] = {};
            #pragma unroll
            for (int tp = 0; tp < 4; tp++) {
                #pragma unroll
                for (int ks = 0; ks < 4; ks++) {
                    uint32_t b00, b01, b10, b11;
                    ldsm4(b00, b01, b10, b11,
                          KS_ + (uint32_t)((krow_f + tp * 16) * KPH + ks * 16 + kcol_f) * 2);
                    mma16(sacc[2 * tp    ], qf[ks], b00, b01);
                    mma16(sacc[2 * tp + 1], qf[ks], b10, b11);
                }
            }

            // causal mask
            if (k0 + 63 > wbase) {
                #pragma unroll
                for (int t = 0; t < 8; t++) {
                    int c = k0 + t * 8 + 2 * tig;
                    if (c     > r0g) sacc[t][0] = -CUDART_INF_F;
                    if (c + 1 > r0g) sacc[t][1] = -CUDART_INF_F;
                    if (c     > r1g) sacc[t][2] = -CUDART_INF_F;
                    if (c + 1 > r1g) sacc[t][3] = -CUDART_INF_F;
                }
            }

            // online softmax (log2 domain)
            float vm0 = -CUDART_INF_F, vm1 = -CUDART_INF_F;
            #pragma unroll
            for (int t = 0; t < 8; t++) {
                vm0 = fmaxf(vm0, fmaxf(sacc[t][0], sacc[t][1]));
                vm1 = fmaxf(vm1, fmaxf(sacc[t][2], sacc[t][3]));
            }
            vm0 = fmaxf(vm0, __shfl_xor_sync(0xffffffffu, vm0, 1));
            vm0 = fmaxf(vm0, __shfl_xor_sync(0xffffffffu, vm0, 2));
            vm1 = fmaxf(vm1, __shfl_xor_sync(0xffffffffu, vm1, 1));
            vm1 = fmaxf(vm1, __shfl_xor_sync(0xffffffffu, vm1, 2));

            float mn0 = fmaxf(m0r, vm0), mn1 = fmaxf(m1r, vm1);
            float al0 = ex2f(m0r - mn0), al1 = ex2f(m1r - mn1);

            // P = 2^(s - mn) in fp16x2 — result IS the PV A-fragment
            uint32_t pf[4][4];
            float sum0 = 0.f, sum1 = 0.f;
            #pragma unroll
            for (int ks = 0; ks < 4; ks++) {
                #pragma unroll
                for (int u = 0; u < 2; u++) {
                    const float* s = sacc[2 * ks + u];
                    uint32_t e01 = ex2_h2(s[0] - mn0, s[1] - mn0);
                    uint32_t e23 = ex2_h2(s[2] - mn1, s[3] - mn1);
                    pf[ks][2 * u    ] = e01;
                    pf[ks][2 * u + 1] = e23;
                    float2 f01 = __half22float2(*(__half2*)&e01);
                    float2 f23 = __half22float2(*(__half2*)&e23);
                    sum0 += f01.x + f01.y;
                    sum1 += f23.x + f23.y;
                }
            }
            sum0 += __shfl_xor_sync(0xffffffffu, sum0, 1);
            sum0 += __shfl_xor_sync(0xffffffffu, sum0, 2);
            sum1 += __shfl_xor_sync(0xffffffffu, sum1, 1);
            sum1 += __shfl_xor_sync(0xffffffffu, sum1, 2);

            l0 = l0 * al0 + sum0;  m0r = mn0;
            l1 = l1 * al1 + sum1;  m1r = mn1;
            #pragma unroll
            for (int dt = 0; dt < 8; dt++) {
                oacc[dt][0] *= al0; oacc[dt][1] *= al0;
                oacc[dt][2] *= al1; oacc[dt][3] *= al1;
            }

            // O += P @ V  — V in natural [key][d], fragments via ldmatrix.trans
            #pragma unroll
            for (int ks = 0; ks < 4; ks++) {
                #pragma unroll
                for (int dp = 0; dp < 4; dp++) {
                    uint32_t b00, b01, b10, b11;
                    ldsm4t(b00, b01, b10, b11,
                           VS_ + (uint32_t)((ks * 16 + vrow_t) * KPH + dp * 16 + vcol_t) * 2);
                    mma16(oacc[2 * dp    ], pf[ks], b00, b01);
                    mma16(oacc[2 * dp + 1], pf[ks], b10, b11);
                }
            }
        }
    }

    // normalize + store ctx (fp16)
    float inv0 = 1.f / l0, inv1 = 1.f / l1;
    #pragma unroll
    for (int dt = 0; dt < 8; dt++) {
        int c = dt * 8 + 2 * tig;
        *(__half2*)&ctx[base + (size_t)r0g * EE + c] =
            __floats2half2_rn(oacc[dt][0] * inv0, oacc[dt][1] * inv0);
        *(__half2*)&ctx[base + (size_t)r1g * EE + c] =
            __floats2half2_rn(oacc[dt][2] * inv1, oacc[dt][3] * inv1);
    }
}

// ---------------------------------------------------------------------------
// Launch
// ---------------------------------------------------------------------------
extern "C" void kernel_launch(void* const* d_in, const int* in_sizes, int n_in,
                              void* d_out, int out_size)
{
    (void)in_sizes; (void)n_in; (void)out_size;
    const float* x  = (const float*)d_in[0];
    const float* Wq = (const float*)d_in[1];
    const float* bq = (const float*)d_in[2];
    const float* Wk = (const float*)d_in[3];
    const float* bk = (const float*)d_in[4];
    const float* Wv = (const float*)d_in[5];
    const float* bv = (const float*)d_in[6];
    const float* Wo = (const float*)d_in[7];
    const float* bo = (const float*)d_in[8];
    float* out = (float*)d_out;

    __half *qp, *kp, *vp, *cp, *xt, *wq, *wk, *wv, *wo;
    cudaGetSymbolAddress((void**)&qp,  g_q);
    cudaGetSymbolAddress((void**)&kp,  g_k);
    cudaGetSymbolAddress((void**)&vp,  g_v);
    cudaGetSymbolAddress((void**)&cp,  g_ctx);
    cudaGetSymbolAddress((void**)&xt,  g_xt);
    cudaGetSymbolAddress((void**)&wq,  g_wq);
    cudaGetSymbolAddress((void**)&wk,  g_wk);
    cudaGetSymbolAddress((void**)&wv,  g_wv);
    cudaGetSymbolAddress((void**)&wo,  g_wo);

    const int xn4 = BB * SS * EE / 4;
    cvt_h<<<xn4 / 256, 256>>>(x, xt, xn4);
    dim3 tb(32, 8);
    transcvt_w4<<<dim3(EE / 32, EE / 32, 4), tb>>>(Wq, Wk, Wv, Wo, wq, wk, wv, wo);

    cudaFuncSetAttribute(gemm16_qkv, cudaFuncAttributeMaxDynamicSharedMemorySize, HSMEM);
    cudaFuncSetAttribute(gemm16_out, cudaFuncAttributeMaxDynamicSharedMemorySize, HSMEM);
    cudaFuncSetAttribute(flash16, cudaFuncAttributeMaxDynamicSharedMemorySize, FSMEM);

    dim3 gqkv(EE / 128, (BB * SS) / 128, 3);
    gemm16_qkv<<<gqkv, 128, HSMEM>>>(xt, wq, bq, wk, bk, wv, bv, qp, kp, vp);

    flash16<<<dim3(SS / 128, HH, BB), 256, FSMEM>>>(qp, kp, vp, cp);

    dim3 go(EE / 128, (BB * SS) / 128);
    gemm16_out<<<go, 128, HSMEM>>>(cp, wo, bo, out);
}